// round 13
// baseline (speedup 1.0000x reference)
#include <cuda_runtime.h>
#include <cuda_bf16.h>
#include <math.h>
#include <stdint.h>

// ---------------------------------------------------------------------------
// Problem constants
// ---------------------------------------------------------------------------
#define Bb 4
#define Tt 24
#define Hh 32
#define Ww 32
#define Dd 128
#define NPOS_PER_B (Tt*Hh*Ww)        // 24576
#define NPOS_TOTAL (Bb*NPOS_PER_B)   // 98304
#define N_CONV 5
#define NUM_FREQS 12
#define N_EXPERTS 7
#define BN_EPS 1e-5f
#define COMBINE_EPS 2.220446049250313e-16f

// ---------------------------------------------------------------------------
// Device scratch
// ---------------------------------------------------------------------------
__device__ __align__(16) __nv_bfloat16 g_xHi[NPOS_TOTAL*128];
__device__ __align__(16) __nv_bfloat16 g_xLo[NPOS_TOTAL*128];
__device__ __align__(16) __nv_bfloat16 g_aHi0[24576*128];
__device__ __align__(16) __nv_bfloat16 g_aLo0[24576*128];
__device__ __align__(16) __nv_bfloat16 g_aHi1[6144*128];
__device__ __align__(16) __nv_bfloat16 g_aLo1[6144*128];
__device__ __align__(16) __nv_bfloat16 g_cwHi[N_CONV*128*512];   // [l][co][k]
__device__ __align__(16) __nv_bfloat16 g_cwLo[N_CONV*128*512];
__device__ float g_gates[Bb*2];
__device__ int   g_eidx [Bb*2];
__device__ __align__(16) __nv_bfloat16 g_wtHi[N_EXPERTS*128*128]; // [e][f][d]
__device__ __align__(16) __nv_bfloat16 g_wtLo[N_EXPERTS*128*128];

__device__ __forceinline__ uint32_t pack_bf16(float a, float b) {
    uint32_t lo = (uint32_t)__bfloat16_as_ushort(__float2bfloat16(a));
    uint32_t hi = (uint32_t)__bfloat16_as_ushort(__float2bfloat16(b));
    return lo | (hi << 16);
}
__device__ __forceinline__ uint32_t smem_u32(const void* p) {
    uint32_t a;
    asm("{ .reg .u64 t; cvta.to.shared.u64 t, %1; cvt.u32.u64 %0, t; }"
        : "=r"(a) : "l"(p));
    return a;
}

// mma.sync m16n8k16 bf16
__device__ __forceinline__ void mma16816(float* d, const uint32_t* a,
                                         uint32_t b0, uint32_t b1) {
    asm volatile(
        "mma.sync.aligned.m16n8k16.row.col.f32.bf16.bf16.f32 "
        "{%0,%1,%2,%3}, {%4,%5,%6,%7}, {%8,%9}, {%0,%1,%2,%3};"
        : "+f"(d[0]), "+f"(d[1]), "+f"(d[2]), "+f"(d[3])
        : "r"(a[0]), "r"(a[1]), "r"(a[2]), "r"(a[3]), "r"(b0), "r"(b1));
}

#define CP_ASYNC16(dst, src) \
    asm volatile("cp.async.cg.shared.global [%0], [%1], 16;" :: "r"(dst), "l"(src))
#define CP_COMMIT() asm volatile("cp.async.commit_group;")
#define CP_WAIT(N)  asm volatile("cp.async.wait_group %0;" :: "n"(N))

// ---------------------------------------------------------------------------
// x split: fp32 -> hi/lo bf16
// ---------------------------------------------------------------------------
__global__ void xsplit_kernel(const float4* __restrict__ x) {
    int idx = blockIdx.x * 256 + threadIdx.x;
    if (idx >= NPOS_TOTAL*32) return;
    float4 v = x[idx];
    __nv_bfloat16 hx = __float2bfloat16(v.x);
    __nv_bfloat16 hy = __float2bfloat16(v.y);
    __nv_bfloat16 hz = __float2bfloat16(v.z);
    __nv_bfloat16 hw = __float2bfloat16(v.w);
    uint2 h = make_uint2(
        (uint32_t)__bfloat16_as_ushort(hx) | ((uint32_t)__bfloat16_as_ushort(hy) << 16),
        (uint32_t)__bfloat16_as_ushort(hz) | ((uint32_t)__bfloat16_as_ushort(hw) << 16));
    uint2 l = make_uint2(
        pack_bf16(v.x - __bfloat162float(hx), v.y - __bfloat162float(hy)),
        pack_bf16(v.z - __bfloat162float(hz), v.w - __bfloat162float(hw)));
    ((uint2*)g_xHi)[idx] = h;
    ((uint2*)g_xLo)[idx] = l;
}

// ---------------------------------------------------------------------------
// Conv weight split + transpose
// ---------------------------------------------------------------------------
__global__ void cwsplit_kernel(const float* __restrict__ cw) {
    int idx = blockIdx.x * 256 + threadIdx.x;
    if (idx >= N_CONV*128*512) return;
    int l   = idx / (128*512);
    int rem = idx - l*128*512;
    int co  = rem >> 9;
    int k   = rem & 511;
    int tap = k >> 7;
    int ci  = k & 127;
    float v = cw[((l*128 + co)*128 + ci)*4 + tap];
    __nv_bfloat16 h = __float2bfloat16(v);
    g_cwHi[idx] = h;
    g_cwLo[idx] = __float2bfloat16(v - __bfloat162float(h));
}

// ---------------------------------------------------------------------------
// Expert weight split + transpose
// ---------------------------------------------------------------------------
__global__ void wsplit_kernel(const float* __restrict__ ew) {
    int idx = blockIdx.x * 256 + threadIdx.x;
    if (idx >= N_EXPERTS*128*128) return;
    int e = idx / 16384;
    int rem = idx - e*16384;
    int d = rem >> 7;
    int f = rem & 127;
    float v = ew[idx];
    __nv_bfloat16 h = __float2bfloat16(v);
    g_wtHi[e*16384 + f*128 + d] = h;
    g_wtLo[e*16384 + f*128 + d] = __float2bfloat16(v - __bfloat162float(h));
}

// ---------------------------------------------------------------------------
// Conv layer via mma.sync split-bf16 (R9 structure; warp-skewed term/ks
// order so post-barrier LDS phases of different warps overlap other warps'
// MMA phases instead of convoying).
// ---------------------------------------------------------------------------
#define STR2 72    // 144 bytes/row
#define CV_A(db, hl)  ((uint32_t)(((db)*2+(hl)) * 9216))
#define CV_B(db, hl)  ((uint32_t)(36864 + ((db)*2+(hl)) * 18432))
#define CV_ROWOFF     110592u
#define CV_BN         111616u
#define CV_SMEM       112640u

__device__ __forceinline__ void conv_issue_chunk(
    uint32_t smb, char* dsm, int db, int chunk,
    const __nv_bfloat16* __restrict__ inHi,
    const __nv_bfloat16* __restrict__ inLo,
    int l, int tid)
{
    const int tap = chunk >> 1;
    const int ciB = (chunk & 1) * 64;
    const int* rowOffS = (const int*)(dsm + CV_ROWOFF);
    #pragma unroll
    for (int j = 0; j < 4; ++j) {
        int i   = tid + j*256;
        int buf = i >> 9;
        int rem = i & 511;
        int r   = rem >> 3, c8 = rem & 7;
        const __nv_bfloat16* src = (buf ? inLo : inHi) + rowOffS[r*4 + tap] + ciB + c8*8;
        uint32_t dst = smb + CV_A(db, buf) + (uint32_t)(r*STR2 + c8*8)*2u;
        CP_ASYNC16(dst, src);
    }
    #pragma unroll
    for (int j = 0; j < 8; ++j) {
        int i   = tid + j*256;
        int buf = i >> 10;
        int rem = i & 1023;
        int n   = rem >> 3, c8 = rem & 7;
        const __nv_bfloat16* src = (buf ? g_cwLo : g_cwHi)
                                 + (size_t)(l*128 + n)*512 + chunk*64 + c8*8;
        uint32_t dst = smb + CV_B(db, buf) + (uint32_t)(n*STR2 + c8*8)*2u;
        CP_ASYNC16(dst, src);
    }
    CP_COMMIT();
}

__global__ __launch_bounds__(256)
void conv_mma_kernel(const __nv_bfloat16* __restrict__ inHi,
                     const __nv_bfloat16* __restrict__ inLo,
                     __nv_bfloat16* __restrict__ outHi,
                     __nv_bfloat16* __restrict__ outLo,
                     int Si, int So, int M, int l,
                     const float* __restrict__ cb,
                     const float* __restrict__ gma,
                     const float* __restrict__ bta,
                     const float* __restrict__ mu,
                     const float* __restrict__ var) {
    extern __shared__ char dsm[];
    const uint32_t smb = smem_u32(dsm);

    const int tid  = threadIdx.x;
    const int wid  = tid >> 5;
    const int lane = tid & 31;
    const int g    = lane >> 2;
    const int t    = lane & 3;
    const int warp_m = wid & 1;
    const int warp_n = wid >> 1;
    const int pm0  = blockIdx.x * 64;

    // warp skew offsets
    const int termOff = wid % 3;
    const int ksOff   = wid & 3;

    int*   rowOffS = (int*)(dsm + CV_ROWOFF);
    float* aCs     = (float*)(dsm + CV_BN);
    float* cCs     = aCs + 128;

    {
        int r = tid >> 2, tap = tid & 3;
        int p = pm0 + r; if (p > M-1) p = M-1;
        int sq = So * So;
        int n  = p / sq;
        int rm = p - n*sq;
        int y  = rm / So;
        int xx = rm - y*So;
        int ky = tap >> 1, kx = tap & 1;
        rowOffS[r*4 + tap] = ((n*Si + 2*y + ky)*Si + (2*xx + kx)) * 128;
    }
    if (tid < 128) {
        float a = gma[tid] * rsqrtf(var[tid] + BN_EPS);
        aCs[tid] = a;
        cCs[tid] = a * (cb[tid] - mu[tid]) + bta[tid];
    }
    __syncthreads();

    conv_issue_chunk(smb, dsm, 0, 0, inHi, inLo, l, tid);

    float acc[2][4][4];
    #pragma unroll
    for (int mt = 0; mt < 2; ++mt)
        #pragma unroll
        for (int nt = 0; nt < 4; ++nt)
            #pragma unroll
            for (int j = 0; j < 4; ++j) acc[mt][nt][j] = 0.f;

    for (int c = 0; c < 8; ++c) {
        if (c < 7) {
            conv_issue_chunk(smb, dsm, (c+1)&1, c+1, inHi, inLo, l, tid);
            CP_WAIT(1);
        } else {
            CP_WAIT(0);
        }
        __syncthreads();

        const int db = c & 1;
        const __nv_bfloat16* Ahi = (const __nv_bfloat16*)(dsm + CV_A(db,0));
        const __nv_bfloat16* Alo = (const __nv_bfloat16*)(dsm + CV_A(db,1));
        const __nv_bfloat16* Bhi = (const __nv_bfloat16*)(dsm + CV_B(db,0));
        const __nv_bfloat16* Blo = (const __nv_bfloat16*)(dsm + CV_B(db,1));

        #pragma unroll
        for (int t3 = 0; t3 < 3; ++t3) {
            int term = t3 + termOff; if (term >= 3) term -= 3;
            const __nv_bfloat16* Ab = (term == 1) ? Alo : Ahi;
            const __nv_bfloat16* Bf = (term == 2) ? Blo : Bhi;
            #pragma unroll
            for (int ks = 0; ks < 4; ++ks) {
                const int k0 = ((ks + ksOff) & 3) * 16;
                uint32_t af[2][4];
                #pragma unroll
                for (int mt = 0; mt < 2; ++mt) {
                    int r0 = warp_m*32 + mt*16 + g;
                    const __nv_bfloat16* ap = Ab + k0 + 2*t;
                    af[mt][0] = *(const uint32_t*)(ap + (size_t)r0*STR2);
                    af[mt][1] = *(const uint32_t*)(ap + (size_t)(r0+8)*STR2);
                    af[mt][2] = *(const uint32_t*)(ap + (size_t)r0*STR2 + 8);
                    af[mt][3] = *(const uint32_t*)(ap + (size_t)(r0+8)*STR2 + 8);
                }
                #pragma unroll
                for (int nt = 0; nt < 4; ++nt) {
                    int n = warp_n*32 + nt*8 + g;
                    const __nv_bfloat16* bp = Bf + (size_t)n*STR2 + k0 + 2*t;
                    uint32_t b0 = *(const uint32_t*)bp;
                    uint32_t b1 = *(const uint32_t*)(bp + 8);
                    mma16816(acc[0][nt], af[0], b0, b1);
                    mma16816(acc[1][nt], af[1], b0, b1);
                }
            }
        }
        __syncthreads();
    }

    uint32_t* oHi = (uint32_t*)outHi;
    uint32_t* oLo = (uint32_t*)outLo;
    #pragma unroll
    for (int mt = 0; mt < 2; ++mt) {
        int r0 = pm0 + warp_m*32 + mt*16 + g;
        #pragma unroll
        for (int nt = 0; nt < 4; ++nt) {
            int col = warp_n*32 + nt*8 + 2*t;
            float a0 = aCs[col], a1 = aCs[col+1];
            float c0 = cCs[col], c1 = cCs[col+1];
            float v00 = acc[mt][nt][0]*a0 + c0; v00 = v00 > 0.f ? v00 : 0.2f*v00;
            float v01 = acc[mt][nt][1]*a1 + c1; v01 = v01 > 0.f ? v01 : 0.2f*v01;
            float v10 = acc[mt][nt][2]*a0 + c0; v10 = v10 > 0.f ? v10 : 0.2f*v10;
            float v11 = acc[mt][nt][3]*a1 + c1; v11 = v11 > 0.f ? v11 : 0.2f*v11;
            if (r0 < M) {
                __nv_bfloat16 h0 = __float2bfloat16(v00);
                __nv_bfloat16 h1 = __float2bfloat16(v01);
                uint32_t hw = (uint32_t)__bfloat16_as_ushort(h0)
                            | ((uint32_t)__bfloat16_as_ushort(h1) << 16);
                uint32_t lw = pack_bf16(v00 - __bfloat162float(h0),
                                        v01 - __bfloat162float(h1));
                oHi[r0*64 + (col>>1)] = hw;
                oLo[r0*64 + (col>>1)] = lw;
            }
            if (r0 + 8 < M) {
                __nv_bfloat16 h0 = __float2bfloat16(v10);
                __nv_bfloat16 h1 = __float2bfloat16(v11);
                uint32_t hw = (uint32_t)__bfloat16_as_ushort(h0)
                            | ((uint32_t)__bfloat16_as_ushort(h1) << 16);
                uint32_t lw = pack_bf16(v10 - __bfloat162float(h0),
                                        v11 - __bfloat162float(h1));
                oHi[(r0+8)*64 + (col>>1)] = hw;
                oLo[(r0+8)*64 + (col>>1)] = lw;
            }
        }
    }
}

// ---------------------------------------------------------------------------
// Gates kernel
// ---------------------------------------------------------------------------
__global__ void gates_kernel(const __nv_bfloat16* __restrict__ zfHi,
                             const __nv_bfloat16* __restrict__ zfLo,
                             const float* __restrict__ fw,
                             const float* __restrict__ fb,
                             const float* __restrict__ wg) {
    __shared__ float s_s[96];
    __shared__ float s_amp[Bb][NUM_FREQS];
    __shared__ float s_log[Bb][N_EXPERTS];

    const int tid  = threadIdx.x;
    const int lane = tid & 31;
    const int warp = tid >> 5;

    for (int r = warp; r < 96; r += 4) {
        float v = 0.f;
        #pragma unroll
        for (int j = 0; j < 4; ++j) {
            int c = lane + j*32;
            float z = __bfloat162float(zfHi[r*128 + c]) + __bfloat162float(zfLo[r*128 + c]);
            v += z * fw[c];
        }
        #pragma unroll
        for (int off = 16; off; off >>= 1)
            v += __shfl_down_sync(0xffffffffu, v, off);
        if (lane == 0) s_s[r] = v + fb[0];
    }
    __syncthreads();

    if (tid < Bb*NUM_FREQS) {
        int b = tid / NUM_FREQS;
        int k = tid % NUM_FREQS + 1;
        float re = 0.f, im = 0.f;
        #pragma unroll
        for (int t = 0; t < Tt; ++t) {
            int m = (k * t) % 24;
            float ang = -(float)M_PI * (float)m / 12.f;
            float sv, cv;
            sincosf(ang, &sv, &cv);
            float x = s_s[b*Tt + t];
            re += x * cv;
            im += x * sv;
        }
        s_amp[b][k-1] = sqrtf(re*re + im*im) * 0.2041241452319315f;
    }
    __syncthreads();

    if (tid < Bb*N_EXPERTS) {
        int b = tid / N_EXPERTS;
        int e = tid % N_EXPERTS;
        float l = 0.f;
        #pragma unroll
        for (int k = 0; k < NUM_FREQS; ++k)
            l += s_amp[b][k] * wg[k*N_EXPERTS + e];
        s_log[b][e] = l;
    }
    __syncthreads();

    if (tid < Bb) {
        int b = tid;
        int i1 = 0; float v1 = s_log[b][0];
        #pragma unroll
        for (int e = 1; e < N_EXPERTS; ++e)
            if (s_log[b][e] > v1) { v1 = s_log[b][e]; i1 = e; }
        int i2 = -1; float v2 = -INFINITY;
        #pragma unroll
        for (int e = 0; e < N_EXPERTS; ++e)
            if (e != i1 && s_log[b][e] > v2) { v2 = s_log[b][e]; i2 = e; }
        float e1 = expf(v2 - v1);
        float den = 1.f + e1;
        g_gates[b*2 + 0] = 1.f / den;
        g_gates[b*2 + 1] = e1 / den;
        g_eidx [b*2 + 0] = i1;
        g_eidx [b*2 + 1] = i2;
    }
}

// ---------------------------------------------------------------------------
// MoE: R9 structure (single-wave persistent, grid (32,4), B resident,
// A 64-wide k-chunks 2-stage, 256 threads, warp tile 64x32) with
// warp-skewed k-step order.
// ---------------------------------------------------------------------------
#define TILES_PER_CTA 6
#define NCHUNK (TILES_PER_CTA*2)          // 12 k-chunks
#define MASTR 72                           // A chunk row stride (elements)
#define MBSTR 136                          // B row stride (elements)
#define MSA(stage, hl) ((uint32_t)((stage)*36864 + (hl)*18432))
#define MSB_BASE 73728u
#define MSB(e, hl)     ((uint32_t)(MSB_BASE + ((e)*2+(hl))*34816))
#define MBIAS 212992u
#define MOE_SMEM 214016u

__device__ __forceinline__ void moe_loadA_chunk(uint32_t smb, int stage,
                                                int row0, int kc, int tid) {
    #pragma unroll
    for (int j = 0; j < 8; ++j) {
        int i  = tid + j*256;            // 2048 uint4: 2hl x 128 rows x 64k
        int hl = i >> 10;
        int rem = i & 1023;
        int r = rem >> 3, c = rem & 7;
        const __nv_bfloat16* src = (hl ? g_xLo : g_xHi)
                                 + (size_t)(row0 + r)*128 + kc*64 + c*8;
        uint32_t dst = smb + MSA(stage, hl) + (uint32_t)(r*MASTR + c*8)*2u;
        CP_ASYNC16(dst, src);
    }
    CP_COMMIT();
}

__global__ __launch_bounds__(256, 1)
void moe_mma_kernel(const float* __restrict__ eb,
                    float* __restrict__ out) {
    extern __shared__ char dsm[];
    const uint32_t smb = smem_u32(dsm);

    const int tid  = threadIdx.x;
    const int wid  = tid >> 5;
    const int lane = tid & 31;
    const int g    = lane >> 2;
    const int t    = lane & 3;
    const int warp_m = wid & 1;     // 2 row groups of 64
    const int warp_n = wid >> 1;    // 4 col groups of 32
    const int bb   = blockIdx.y;
    const int ksOff = wid & 3;      // warp skew

    const int e0 = g_eidx[bb*2 + 0];
    const int e1 = g_eidx[bb*2 + 1];
    const float g0 = g_gates[bb*2 + 0];
    const float g1 = g_gates[bb*2 + 1];
    const int eArr[2] = {e0, e1};

    const int pmBase = bb*NPOS_PER_B + blockIdx.x * (128*TILES_PER_CTA);

    float* biasSm = (float*)(dsm + MBIAS);
    {
        int s = tid >> 7, f = tid & 127;
        biasSm[tid] = eb[eArr[s]*128 + f];
    }

    // prologue: A chunk0, B (all), A chunk1
    moe_loadA_chunk(smb, 0, pmBase, 0, tid);
    #pragma unroll
    for (int j = 0; j < 32; ++j) {
        int i  = tid + j*256;            // 8192 uint4
        int buf = i >> 11;               // e*2+hl
        int rem = i & 2047;
        int n = rem >> 4, c = rem & 15;
        int e = buf >> 1, hl = buf & 1;
        const __nv_bfloat16* src = (hl ? g_wtLo : g_wtHi)
                                 + (size_t)eArr[e]*16384 + n*128 + c*8;
        uint32_t dst = smb + MSB(e, hl) + (uint32_t)(n*MBSTR + c*8)*2u;
        CP_ASYNC16(dst, src);
    }
    CP_COMMIT();
    moe_loadA_chunk(smb, 1, pmBase, 1, tid);

    float acc[2][4][4][4];   // [expert][mt][nt][j]

    for (int ci = 0; ci < NCHUNK; ++ci) {
        const int tile  = ci >> 1;
        const int kc    = ci & 1;
        const int stage = ci & 1;
        const int pm0   = pmBase + tile*128;

        if (ci < NCHUNK-1) { CP_WAIT(1); } else { CP_WAIT(0); }
        __syncthreads();

        if (kc == 0) {
            #pragma unroll
            for (int s = 0; s < 2; ++s)
                #pragma unroll
                for (int mt = 0; mt < 4; ++mt)
                    #pragma unroll
                    for (int nt = 0; nt < 4; ++nt)
                        #pragma unroll
                        for (int j = 0; j < 4; ++j) acc[s][mt][nt][j] = 0.f;
        }

        const __nv_bfloat16* Ahi = (const __nv_bfloat16*)(dsm + MSA(stage, 0));
        const __nv_bfloat16* Alo = (const __nv_bfloat16*)(dsm + MSA(stage, 1));
        const __nv_bfloat16* Bhi0 = (const __nv_bfloat16*)(dsm + MSB(0,0));
        const __nv_bfloat16* Blo0 = (const __nv_bfloat16*)(dsm + MSB(0,1));
        const __nv_bfloat16* Bhi1 = (const __nv_bfloat16*)(dsm + MSB(1,0));
        const __nv_bfloat16* Blo1 = (const __nv_bfloat16*)(dsm + MSB(1,1));

        #pragma unroll
        for (int ks = 0; ks < 4; ++ks) {
            const int k0 = ((ks + ksOff) & 3) * 16;   // within chunk (skewed)
            const int kg = kc*64 + k0;                // global k (for B)
            uint32_t a[2][4][4];                      // [hl][mt][4]
            #pragma unroll
            for (int mt = 0; mt < 4; ++mt) {
                int r0 = warp_m*64 + mt*16 + g;
                const __nv_bfloat16* apH = Ahi + k0 + 2*t;
                const __nv_bfloat16* apL = Alo + k0 + 2*t;
                a[0][mt][0] = *(const uint32_t*)(apH + (size_t)r0*MASTR);
                a[0][mt][1] = *(const uint32_t*)(apH + (size_t)(r0+8)*MASTR);
                a[0][mt][2] = *(const uint32_t*)(apH + (size_t)r0*MASTR + 8);
                a[0][mt][3] = *(const uint32_t*)(apH + (size_t)(r0+8)*MASTR + 8);
                a[1][mt][0] = *(const uint32_t*)(apL + (size_t)r0*MASTR);
                a[1][mt][1] = *(const uint32_t*)(apL + (size_t)(r0+8)*MASTR);
                a[1][mt][2] = *(const uint32_t*)(apL + (size_t)r0*MASTR + 8);
                a[1][mt][3] = *(const uint32_t*)(apL + (size_t)(r0+8)*MASTR + 8);
            }
            #pragma unroll
            for (int s = 0; s < 2; ++s) {
                const __nv_bfloat16* BH = s ? Bhi1 : Bhi0;
                const __nv_bfloat16* BL = s ? Blo1 : Blo0;
                uint32_t bfr[2][4][2];            // [hl][nt][2]
                #pragma unroll
                for (int nt = 0; nt < 4; ++nt) {
                    int n = warp_n*32 + nt*8 + g;
                    const __nv_bfloat16* bpH = BH + (size_t)n*MBSTR + kg + 2*t;
                    const __nv_bfloat16* bpL = BL + (size_t)n*MBSTR + kg + 2*t;
                    bfr[0][nt][0] = *(const uint32_t*)bpH;
                    bfr[0][nt][1] = *(const uint32_t*)(bpH + 8);
                    bfr[1][nt][0] = *(const uint32_t*)bpL;
                    bfr[1][nt][1] = *(const uint32_t*)(bpL + 8);
                }
                #pragma unroll
                for (int mt = 0; mt < 4; ++mt)
                    #pragma unroll
                    for (int nt = 0; nt < 4; ++nt) {
                        mma16816(acc[s][mt][nt], a[0][mt], bfr[0][nt][0], bfr[0][nt][1]);
                        mma16816(acc[s][mt][nt], a[1][mt], bfr[0][nt][0], bfr[0][nt][1]);
                        mma16816(acc[s][mt][nt], a[0][mt], bfr[1][nt][0], bfr[1][nt][1]);
                    }
            }
        }
        __syncthreads();

        // issue chunk ci+2 into this (now free) stage; overlaps next compute
        // and (for kc==1) the epilogue below.
        if (ci + 2 < NCHUNK) {
            int nci = ci + 2;
            moe_loadA_chunk(smb, nci & 1, pmBase + (nci >> 1)*128, nci & 1, tid);
        }

        if (kc == 1) {
            // epilogue: out = v0 + log(g0 + g1*exp(v1 - v0))
            #pragma unroll
            for (int mt = 0; mt < 4; ++mt) {
                int row = pm0 + warp_m*64 + mt*16 + g;
                #pragma unroll
                for (int nt = 0; nt < 4; ++nt) {
                    int col0 = warp_n*32 + nt*8 + 2*t;
                    float b00 = biasSm[col0],       b01 = biasSm[col0 + 1];
                    float b10 = biasSm[128 + col0], b11 = biasSm[128 + col0 + 1];
                    float o[4];
                    #pragma unroll
                    for (int j = 0; j < 4; ++j) {
                        float v0 = acc[0][mt][nt][j] + ((j & 1) ? b01 : b00);
                        float v1 = acc[1][mt][nt][j] + ((j & 1) ? b11 : b10);
                        o[j] = v0 + __logf(g0 + g1 * __expf(v1 - v0));
                    }
                    *(float2*)&out[(size_t)row*128 + col0]     = make_float2(o[0], o[1]);
                    *(float2*)&out[(size_t)(row+8)*128 + col0] = make_float2(o[2], o[3]);
                }
            }
        }
    }
}

// ---------------------------------------------------------------------------
// Launch
// ---------------------------------------------------------------------------
extern "C" void kernel_launch(void* const* d_in, const int* in_sizes, int n_in,
                              void* d_out, int out_size) {
    const float* x        = (const float*)d_in[0];
    const float* conv_w   = (const float*)d_in[1];
    const float* conv_b   = (const float*)d_in[2];
    const float* bn_gamma = (const float*)d_in[3];
    const float* bn_beta  = (const float*)d_in[4];
    const float* bn_mean  = (const float*)d_in[5];
    const float* bn_var   = (const float*)d_in[6];
    const float* fuse_w   = (const float*)d_in[7];
    const float* fuse_b   = (const float*)d_in[8];
    const float* w_gate   = (const float*)d_in[9];
    const float* expert_w = (const float*)d_in[10];
    const float* expert_b = (const float*)d_in[11];
    float* out = (float*)d_out;

    __nv_bfloat16 *xHi, *xLo, *aHi0, *aLo0, *aHi1, *aLo1;
    cudaGetSymbolAddress((void**)&xHi,  g_xHi);
    cudaGetSymbolAddress((void**)&xLo,  g_xLo);
    cudaGetSymbolAddress((void**)&aHi0, g_aHi0);
    cudaGetSymbolAddress((void**)&aLo0, g_aLo0);
    cudaGetSymbolAddress((void**)&aHi1, g_aHi1);
    cudaGetSymbolAddress((void**)&aLo1, g_aLo1);

    cudaFuncSetAttribute(conv_mma_kernel,
                         cudaFuncAttributeMaxDynamicSharedMemorySize, CV_SMEM);
    cudaFuncSetAttribute(moe_mma_kernel,
                         cudaFuncAttributeMaxDynamicSharedMemorySize, MOE_SMEM);

    xsplit_kernel<<<(NPOS_TOTAL*32 + 255)/256, 256>>>((const float4*)x);
    cwsplit_kernel<<<(N_CONV*128*512 + 255)/256, 256>>>(conv_w);
    wsplit_kernel<<<(N_EXPERTS*128*128 + 255)/256, 256>>>(expert_w);

    const __nv_bfloat16* iH = xHi;
    const __nv_bfloat16* iL = xLo;
    int Si = 32;
    for (int l = 0; l < N_CONV; ++l) {
        int So = Si >> 1;
        int M  = 96 * So * So;
        __nv_bfloat16* oH = (l & 1) ? aHi1 : aHi0;
        __nv_bfloat16* oL = (l & 1) ? aLo1 : aLo0;
        int grid = (M + 63) / 64;
        conv_mma_kernel<<<grid, 256, CV_SMEM>>>(iH, iL, oH, oL, Si, So, M, l,
                                                conv_b   + l*128,
                                                bn_gamma + l*128,
                                                bn_beta  + l*128,
                                                bn_mean  + l*128,
                                                bn_var   + l*128);
        iH = oH; iL = oL;
        Si = So;
    }

    gates_kernel<<<1, 128>>>(aHi0, aLo0, fuse_w, fuse_b, w_gate);

    dim3 moeGrid(32, Bb);
    moe_mma_kernel<<<moeGrid, 256, MOE_SMEM>>>(expert_b, out);
}

// round 14
// speedup vs baseline: 1.0990x; 1.0990x over previous
#include <cuda_runtime.h>
#include <cuda_bf16.h>
#include <math.h>
#include <stdint.h>

// ---------------------------------------------------------------------------
// Problem constants
// ---------------------------------------------------------------------------
#define Bb 4
#define Tt 24
#define Hh 32
#define Ww 32
#define Dd 128
#define NPOS_PER_B (Tt*Hh*Ww)        // 24576
#define NPOS_TOTAL (Bb*NPOS_PER_B)   // 98304
#define N_CONV 5
#define NUM_FREQS 12
#define N_EXPERTS 7
#define BN_EPS 1e-5f
#define COMBINE_EPS 2.220446049250313e-16f

// ---------------------------------------------------------------------------
// Device scratch
// ---------------------------------------------------------------------------
__device__ __align__(16) __nv_bfloat16 g_xHi[NPOS_TOTAL*128];
__device__ __align__(16) __nv_bfloat16 g_xLo[NPOS_TOTAL*128];
__device__ __align__(16) __nv_bfloat16 g_aHi0[24576*128];
__device__ __align__(16) __nv_bfloat16 g_aLo0[24576*128];
__device__ __align__(16) __nv_bfloat16 g_aHi1[6144*128];
__device__ __align__(16) __nv_bfloat16 g_aLo1[6144*128];
__device__ __align__(16) __nv_bfloat16 g_cwHi[N_CONV*128*512];   // [l][co][k]
__device__ __align__(16) __nv_bfloat16 g_cwLo[N_CONV*128*512];
__device__ float g_gates[Bb*2];
__device__ int   g_eidx [Bb*2];
__device__ __align__(16) __nv_bfloat16 g_wtHi[N_EXPERTS*128*128]; // [e][f][d]
__device__ __align__(16) __nv_bfloat16 g_wtLo[N_EXPERTS*128*128];

__device__ __forceinline__ uint32_t pack_bf16(float a, float b) {
    uint32_t lo = (uint32_t)__bfloat16_as_ushort(__float2bfloat16(a));
    uint32_t hi = (uint32_t)__bfloat16_as_ushort(__float2bfloat16(b));
    return lo | (hi << 16);
}
__device__ __forceinline__ uint32_t smem_u32(const void* p) {
    uint32_t a;
    asm("{ .reg .u64 t; cvta.to.shared.u64 t, %1; cvt.u32.u64 %0, t; }"
        : "=r"(a) : "l"(p));
    return a;
}

// mma.sync m16n8k16 bf16
__device__ __forceinline__ void mma16816(float* d, const uint32_t* a,
                                         uint32_t b0, uint32_t b1) {
    asm volatile(
        "mma.sync.aligned.m16n8k16.row.col.f32.bf16.bf16.f32 "
        "{%0,%1,%2,%3}, {%4,%5,%6,%7}, {%8,%9}, {%0,%1,%2,%3};"
        : "+f"(d[0]), "+f"(d[1]), "+f"(d[2]), "+f"(d[3])
        : "r"(a[0]), "r"(a[1]), "r"(a[2]), "r"(a[3]), "r"(b0), "r"(b1));
}

#define CP_ASYNC16(dst, src) \
    asm volatile("cp.async.cg.shared.global [%0], [%1], 16;" :: "r"(dst), "l"(src))
#define CP_COMMIT() asm volatile("cp.async.commit_group;")
#define CP_WAIT(N)  asm volatile("cp.async.wait_group %0;" :: "n"(N))

// ---------------------------------------------------------------------------
// x split: fp32 -> hi/lo bf16
// ---------------------------------------------------------------------------
__global__ void xsplit_kernel(const float4* __restrict__ x) {
    int idx = blockIdx.x * 256 + threadIdx.x;
    if (idx >= NPOS_TOTAL*32) return;
    float4 v = x[idx];
    __nv_bfloat16 hx = __float2bfloat16(v.x);
    __nv_bfloat16 hy = __float2bfloat16(v.y);
    __nv_bfloat16 hz = __float2bfloat16(v.z);
    __nv_bfloat16 hw = __float2bfloat16(v.w);
    uint2 h = make_uint2(
        (uint32_t)__bfloat16_as_ushort(hx) | ((uint32_t)__bfloat16_as_ushort(hy) << 16),
        (uint32_t)__bfloat16_as_ushort(hz) | ((uint32_t)__bfloat16_as_ushort(hw) << 16));
    uint2 l = make_uint2(
        pack_bf16(v.x - __bfloat162float(hx), v.y - __bfloat162float(hy)),
        pack_bf16(v.z - __bfloat162float(hz), v.w - __bfloat162float(hw)));
    ((uint2*)g_xHi)[idx] = h;
    ((uint2*)g_xLo)[idx] = l;
}

// ---------------------------------------------------------------------------
// Conv weight split + transpose
// ---------------------------------------------------------------------------
__global__ void cwsplit_kernel(const float* __restrict__ cw) {
    int idx = blockIdx.x * 256 + threadIdx.x;
    if (idx >= N_CONV*128*512) return;
    int l   = idx / (128*512);
    int rem = idx - l*128*512;
    int co  = rem >> 9;
    int k   = rem & 511;
    int tap = k >> 7;
    int ci  = k & 127;
    float v = cw[((l*128 + co)*128 + ci)*4 + tap];
    __nv_bfloat16 h = __float2bfloat16(v);
    g_cwHi[idx] = h;
    g_cwLo[idx] = __float2bfloat16(v - __bfloat162float(h));
}

// ---------------------------------------------------------------------------
// Expert weight split + transpose
// ---------------------------------------------------------------------------
__global__ void wsplit_kernel(const float* __restrict__ ew) {
    int idx = blockIdx.x * 256 + threadIdx.x;
    if (idx >= N_EXPERTS*128*128) return;
    int e = idx / 16384;
    int rem = idx - e*16384;
    int d = rem >> 7;
    int f = rem & 127;
    float v = ew[idx];
    __nv_bfloat16 h = __float2bfloat16(v);
    g_wtHi[e*16384 + f*128 + d] = h;
    g_wtLo[e*16384 + f*128 + d] = __float2bfloat16(v - __bfloat162float(h));
}

// ---------------------------------------------------------------------------
// Conv layer 1: BM=64 (R9 champion, unchanged).
// ---------------------------------------------------------------------------
#define STR2 72    // 144 bytes/row
#define CV_A(db, hl)  ((uint32_t)(((db)*2+(hl)) * 9216))
#define CV_B(db, hl)  ((uint32_t)(36864 + ((db)*2+(hl)) * 18432))
#define CV_ROWOFF     110592u
#define CV_BN         111616u
#define CV_SMEM       112640u

__device__ __forceinline__ void conv_issue_chunk(
    uint32_t smb, char* dsm, int db, int chunk,
    const __nv_bfloat16* __restrict__ inHi,
    const __nv_bfloat16* __restrict__ inLo,
    int l, int tid)
{
    const int tap = chunk >> 1;
    const int ciB = (chunk & 1) * 64;
    const int* rowOffS = (const int*)(dsm + CV_ROWOFF);
    #pragma unroll
    for (int j = 0; j < 4; ++j) {
        int i   = tid + j*256;
        int buf = i >> 9;
        int rem = i & 511;
        int r   = rem >> 3, c8 = rem & 7;
        const __nv_bfloat16* src = (buf ? inLo : inHi) + rowOffS[r*4 + tap] + ciB + c8*8;
        uint32_t dst = smb + CV_A(db, buf) + (uint32_t)(r*STR2 + c8*8)*2u;
        CP_ASYNC16(dst, src);
    }
    #pragma unroll
    for (int j = 0; j < 8; ++j) {
        int i   = tid + j*256;
        int buf = i >> 10;
        int rem = i & 1023;
        int n   = rem >> 3, c8 = rem & 7;
        const __nv_bfloat16* src = (buf ? g_cwLo : g_cwHi)
                                 + (size_t)(l*128 + n)*512 + chunk*64 + c8*8;
        uint32_t dst = smb + CV_B(db, buf) + (uint32_t)(n*STR2 + c8*8)*2u;
        CP_ASYNC16(dst, src);
    }
    CP_COMMIT();
}

__global__ __launch_bounds__(256)
void conv_mma_kernel(const __nv_bfloat16* __restrict__ inHi,
                     const __nv_bfloat16* __restrict__ inLo,
                     __nv_bfloat16* __restrict__ outHi,
                     __nv_bfloat16* __restrict__ outLo,
                     int Si, int So, int M, int l,
                     const float* __restrict__ cb,
                     const float* __restrict__ gma,
                     const float* __restrict__ bta,
                     const float* __restrict__ mu,
                     const float* __restrict__ var) {
    extern __shared__ char dsm[];
    const uint32_t smb = smem_u32(dsm);

    const int tid  = threadIdx.x;
    const int wid  = tid >> 5;
    const int lane = tid & 31;
    const int g    = lane >> 2;
    const int t    = lane & 3;
    const int warp_m = wid & 1;
    const int warp_n = wid >> 1;
    const int pm0  = blockIdx.x * 64;

    int*   rowOffS = (int*)(dsm + CV_ROWOFF);
    float* aCs     = (float*)(dsm + CV_BN);
    float* cCs     = aCs + 128;

    {
        int r = tid >> 2, tap = tid & 3;
        int p = pm0 + r; if (p > M-1) p = M-1;
        int sq = So * So;
        int n  = p / sq;
        int rm = p - n*sq;
        int y  = rm / So;
        int xx = rm - y*So;
        int ky = tap >> 1, kx = tap & 1;
        rowOffS[r*4 + tap] = ((n*Si + 2*y + ky)*Si + (2*xx + kx)) * 128;
    }
    if (tid < 128) {
        float a = gma[tid] * rsqrtf(var[tid] + BN_EPS);
        aCs[tid] = a;
        cCs[tid] = a * (cb[tid] - mu[tid]) + bta[tid];
    }
    __syncthreads();

    conv_issue_chunk(smb, dsm, 0, 0, inHi, inLo, l, tid);

    float acc[2][4][4];
    #pragma unroll
    for (int mt = 0; mt < 2; ++mt)
        #pragma unroll
        for (int nt = 0; nt < 4; ++nt)
            #pragma unroll
            for (int j = 0; j < 4; ++j) acc[mt][nt][j] = 0.f;

    for (int c = 0; c < 8; ++c) {
        if (c < 7) {
            conv_issue_chunk(smb, dsm, (c+1)&1, c+1, inHi, inLo, l, tid);
            CP_WAIT(1);
        } else {
            CP_WAIT(0);
        }
        __syncthreads();

        const int db = c & 1;
        const __nv_bfloat16* Ahi = (const __nv_bfloat16*)(dsm + CV_A(db,0));
        const __nv_bfloat16* Alo = (const __nv_bfloat16*)(dsm + CV_A(db,1));
        const __nv_bfloat16* Bhi = (const __nv_bfloat16*)(dsm + CV_B(db,0));
        const __nv_bfloat16* Blo = (const __nv_bfloat16*)(dsm + CV_B(db,1));

        #pragma unroll
        for (int term = 0; term < 3; ++term) {
            const __nv_bfloat16* Ab = (term == 1) ? Alo : Ahi;
            const __nv_bfloat16* Bf = (term == 2) ? Blo : Bhi;
            #pragma unroll
            for (int ks = 0; ks < 4; ++ks) {
                const int k0 = ks*16;
                uint32_t af[2][4];
                #pragma unroll
                for (int mt = 0; mt < 2; ++mt) {
                    int r0 = warp_m*32 + mt*16 + g;
                    const __nv_bfloat16* ap = Ab + k0 + 2*t;
                    af[mt][0] = *(const uint32_t*)(ap + (size_t)r0*STR2);
                    af[mt][1] = *(const uint32_t*)(ap + (size_t)(r0+8)*STR2);
                    af[mt][2] = *(const uint32_t*)(ap + (size_t)r0*STR2 + 8);
                    af[mt][3] = *(const uint32_t*)(ap + (size_t)(r0+8)*STR2 + 8);
                }
                #pragma unroll
                for (int nt = 0; nt < 4; ++nt) {
                    int n = warp_n*32 + nt*8 + g;
                    const __nv_bfloat16* bp = Bf + (size_t)n*STR2 + k0 + 2*t;
                    uint32_t b0 = *(const uint32_t*)bp;
                    uint32_t b1 = *(const uint32_t*)(bp + 8);
                    mma16816(acc[0][nt], af[0], b0, b1);
                    mma16816(acc[1][nt], af[1], b0, b1);
                }
            }
        }
        __syncthreads();
    }

    uint32_t* oHi = (uint32_t*)outHi;
    uint32_t* oLo = (uint32_t*)outLo;
    #pragma unroll
    for (int mt = 0; mt < 2; ++mt) {
        int r0 = pm0 + warp_m*32 + mt*16 + g;
        #pragma unroll
        for (int nt = 0; nt < 4; ++nt) {
            int col = warp_n*32 + nt*8 + 2*t;
            float a0 = aCs[col], a1 = aCs[col+1];
            float c0 = cCs[col], c1 = cCs[col+1];
            float v00 = acc[mt][nt][0]*a0 + c0; v00 = v00 > 0.f ? v00 : 0.2f*v00;
            float v01 = acc[mt][nt][1]*a1 + c1; v01 = v01 > 0.f ? v01 : 0.2f*v01;
            float v10 = acc[mt][nt][2]*a0 + c0; v10 = v10 > 0.f ? v10 : 0.2f*v10;
            float v11 = acc[mt][nt][3]*a1 + c1; v11 = v11 > 0.f ? v11 : 0.2f*v11;
            if (r0 < M) {
                __nv_bfloat16 h0 = __float2bfloat16(v00);
                __nv_bfloat16 h1 = __float2bfloat16(v01);
                uint32_t hw = (uint32_t)__bfloat16_as_ushort(h0)
                            | ((uint32_t)__bfloat16_as_ushort(h1) << 16);
                uint32_t lw = pack_bf16(v00 - __bfloat162float(h0),
                                        v01 - __bfloat162float(h1));
                oHi[r0*64 + (col>>1)] = hw;
                oLo[r0*64 + (col>>1)] = lw;
            }
            if (r0 + 8 < M) {
                __nv_bfloat16 h0 = __float2bfloat16(v10);
                __nv_bfloat16 h1 = __float2bfloat16(v11);
                uint32_t hw = (uint32_t)__bfloat16_as_ushort(h0)
                            | ((uint32_t)__bfloat16_as_ushort(h1) << 16);
                uint32_t lw = pack_bf16(v10 - __bfloat162float(h0),
                                        v11 - __bfloat162float(h1));
                oHi[(r0+8)*64 + (col>>1)] = hw;
                oLo[(r0+8)*64 + (col>>1)] = lw;
            }
        }
    }
}

// ---------------------------------------------------------------------------
// Conv layers 2-5: BM=16 variant. 4x the CTA parallelism; per-CTA critical
// path /4. 8 warps, warp tile 16x16 (nt=2). Same K-chunk pipeline & math.
// ---------------------------------------------------------------------------
#define CS_STG 41472u
#define CS_A(db, hl) ((uint32_t)((db)*CS_STG + (hl)*2304u))
#define CS_B(db, hl) ((uint32_t)((db)*CS_STG + 4608u + (hl)*18432u))
#define CS_ROWOFF 82944u
#define CS_BN     83200u
#define CS_SMEM   84224u

__device__ __forceinline__ void convs_issue_chunk(
    uint32_t smb, char* dsm, int db, int chunk,
    const __nv_bfloat16* __restrict__ inHi,
    const __nv_bfloat16* __restrict__ inLo,
    int l, int tid)
{
    const int tap = chunk >> 1;
    const int ciB = (chunk & 1) * 64;
    const int* rowOffS = (const int*)(dsm + CS_ROWOFF);
    // A: 256 uint4 (hi 128 + lo 128): 16 rows x 64 k  -> 1 per thread
    {
        int i   = tid;
        int buf = i >> 7;
        int rem = i & 127;
        int r   = rem >> 3, c8 = rem & 7;
        const __nv_bfloat16* src = (buf ? inLo : inHi) + rowOffS[r*4 + tap] + ciB + c8*8;
        uint32_t dst = smb + CS_A(db, buf) + (uint32_t)(r*STR2 + c8*8)*2u;
        CP_ASYNC16(dst, src);
    }
    // B: 2048 uint4 (hi 1024 + lo 1024): 128 co x 64 k
    #pragma unroll
    for (int j = 0; j < 8; ++j) {
        int i   = tid + j*256;
        int buf = i >> 10;
        int rem = i & 1023;
        int n   = rem >> 3, c8 = rem & 7;
        const __nv_bfloat16* src = (buf ? g_cwLo : g_cwHi)
                                 + (size_t)(l*128 + n)*512 + chunk*64 + c8*8;
        uint32_t dst = smb + CS_B(db, buf) + (uint32_t)(n*STR2 + c8*8)*2u;
        CP_ASYNC16(dst, src);
    }
    CP_COMMIT();
}

__global__ __launch_bounds__(256)
void conv_mma_small(const __nv_bfloat16* __restrict__ inHi,
                    const __nv_bfloat16* __restrict__ inLo,
                    __nv_bfloat16* __restrict__ outHi,
                    __nv_bfloat16* __restrict__ outLo,
                    int Si, int So, int M, int l,
                    const float* __restrict__ cb,
                    const float* __restrict__ gma,
                    const float* __restrict__ bta,
                    const float* __restrict__ mu,
                    const float* __restrict__ var) {
    extern __shared__ char dsm[];
    const uint32_t smb = smem_u32(dsm);

    const int tid  = threadIdx.x;
    const int wid  = tid >> 5;       // 8 col groups of 16
    const int lane = tid & 31;
    const int g    = lane >> 2;
    const int t    = lane & 3;
    const int pm0  = blockIdx.x * 16;

    int*   rowOffS = (int*)(dsm + CS_ROWOFF);
    float* aCs     = (float*)(dsm + CS_BN);
    float* cCs     = aCs + 128;

    if (tid < 64) {
        int r = tid >> 2, tap = tid & 3;
        int p = pm0 + r; if (p > M-1) p = M-1;
        int sq = So * So;
        int n  = p / sq;
        int rm = p - n*sq;
        int y  = rm / So;
        int xx = rm - y*So;
        int ky = tap >> 1, kx = tap & 1;
        rowOffS[r*4 + tap] = ((n*Si + 2*y + ky)*Si + (2*xx + kx)) * 128;
    }
    if (tid < 128) {
        float a = gma[tid] * rsqrtf(var[tid] + BN_EPS);
        aCs[tid] = a;
        cCs[tid] = a * (cb[tid] - mu[tid]) + bta[tid];
    }
    __syncthreads();

    convs_issue_chunk(smb, dsm, 0, 0, inHi, inLo, l, tid);

    float acc[2][4];          // [nt][j]
    #pragma unroll
    for (int nt = 0; nt < 2; ++nt)
        #pragma unroll
        for (int j = 0; j < 4; ++j) acc[nt][j] = 0.f;

    for (int c = 0; c < 8; ++c) {
        if (c < 7) {
            convs_issue_chunk(smb, dsm, (c+1)&1, c+1, inHi, inLo, l, tid);
            CP_WAIT(1);
        } else {
            CP_WAIT(0);
        }
        __syncthreads();

        const int db = c & 1;
        const __nv_bfloat16* Ahi = (const __nv_bfloat16*)(dsm + CS_A(db,0));
        const __nv_bfloat16* Alo = (const __nv_bfloat16*)(dsm + CS_A(db,1));
        const __nv_bfloat16* Bhi = (const __nv_bfloat16*)(dsm + CS_B(db,0));
        const __nv_bfloat16* Blo = (const __nv_bfloat16*)(dsm + CS_B(db,1));

        #pragma unroll
        for (int term = 0; term < 3; ++term) {
            const __nv_bfloat16* Ab = (term == 1) ? Alo : Ahi;
            const __nv_bfloat16* Bf = (term == 2) ? Blo : Bhi;
            #pragma unroll
            for (int ks = 0; ks < 4; ++ks) {
                const int k0 = ks*16;
                uint32_t af[4];
                const __nv_bfloat16* ap = Ab + k0 + 2*t;
                af[0] = *(const uint32_t*)(ap + (size_t)g*STR2);
                af[1] = *(const uint32_t*)(ap + (size_t)(g+8)*STR2);
                af[2] = *(const uint32_t*)(ap + (size_t)g*STR2 + 8);
                af[3] = *(const uint32_t*)(ap + (size_t)(g+8)*STR2 + 8);
                #pragma unroll
                for (int nt = 0; nt < 2; ++nt) {
                    int n = wid*16 + nt*8 + g;
                    const __nv_bfloat16* bp = Bf + (size_t)n*STR2 + k0 + 2*t;
                    uint32_t b0 = *(const uint32_t*)bp;
                    uint32_t b1 = *(const uint32_t*)(bp + 8);
                    mma16816(acc[nt], af, b0, b1);
                }
            }
        }
        __syncthreads();
    }

    uint32_t* oHi = (uint32_t*)outHi;
    uint32_t* oLo = (uint32_t*)outLo;
    {
        int r0 = pm0 + g;
        #pragma unroll
        for (int nt = 0; nt < 2; ++nt) {
            int col = wid*16 + nt*8 + 2*t;
            float a0 = aCs[col], a1 = aCs[col+1];
            float c0 = cCs[col], c1 = cCs[col+1];
            float v00 = acc[nt][0]*a0 + c0; v00 = v00 > 0.f ? v00 : 0.2f*v00;
            float v01 = acc[nt][1]*a1 + c1; v01 = v01 > 0.f ? v01 : 0.2f*v01;
            float v10 = acc[nt][2]*a0 + c0; v10 = v10 > 0.f ? v10 : 0.2f*v10;
            float v11 = acc[nt][3]*a1 + c1; v11 = v11 > 0.f ? v11 : 0.2f*v11;
            {
                __nv_bfloat16 h0 = __float2bfloat16(v00);
                __nv_bfloat16 h1 = __float2bfloat16(v01);
                uint32_t hw = (uint32_t)__bfloat16_as_ushort(h0)
                            | ((uint32_t)__bfloat16_as_ushort(h1) << 16);
                uint32_t lw = pack_bf16(v00 - __bfloat162float(h0),
                                        v01 - __bfloat162float(h1));
                oHi[r0*64 + (col>>1)] = hw;
                oLo[r0*64 + (col>>1)] = lw;
            }
            {
                __nv_bfloat16 h0 = __float2bfloat16(v10);
                __nv_bfloat16 h1 = __float2bfloat16(v11);
                uint32_t hw = (uint32_t)__bfloat16_as_ushort(h0)
                            | ((uint32_t)__bfloat16_as_ushort(h1) << 16);
                uint32_t lw = pack_bf16(v10 - __bfloat162float(h0),
                                        v11 - __bfloat162float(h1));
                oHi[(r0+8)*64 + (col>>1)] = hw;
                oLo[(r0+8)*64 + (col>>1)] = lw;
            }
        }
    }
}

// ---------------------------------------------------------------------------
// Gates kernel
// ---------------------------------------------------------------------------
__global__ void gates_kernel(const __nv_bfloat16* __restrict__ zfHi,
                             const __nv_bfloat16* __restrict__ zfLo,
                             const float* __restrict__ fw,
                             const float* __restrict__ fb,
                             const float* __restrict__ wg) {
    __shared__ float s_s[96];
    __shared__ float s_amp[Bb][NUM_FREQS];
    __shared__ float s_log[Bb][N_EXPERTS];

    const int tid  = threadIdx.x;
    const int lane = tid & 31;
    const int warp = tid >> 5;

    for (int r = warp; r < 96; r += 4) {
        float v = 0.f;
        #pragma unroll
        for (int j = 0; j < 4; ++j) {
            int c = lane + j*32;
            float z = __bfloat162float(zfHi[r*128 + c]) + __bfloat162float(zfLo[r*128 + c]);
            v += z * fw[c];
        }
        #pragma unroll
        for (int off = 16; off; off >>= 1)
            v += __shfl_down_sync(0xffffffffu, v, off);
        if (lane == 0) s_s[r] = v + fb[0];
    }
    __syncthreads();

    if (tid < Bb*NUM_FREQS) {
        int b = tid / NUM_FREQS;
        int k = tid % NUM_FREQS + 1;
        float re = 0.f, im = 0.f;
        #pragma unroll
        for (int t = 0; t < Tt; ++t) {
            int m = (k * t) % 24;
            float ang = -(float)M_PI * (float)m / 12.f;
            float sv, cv;
            sincosf(ang, &sv, &cv);
            float x = s_s[b*Tt + t];
            re += x * cv;
            im += x * sv;
        }
        s_amp[b][k-1] = sqrtf(re*re + im*im) * 0.2041241452319315f;
    }
    __syncthreads();

    if (tid < Bb*N_EXPERTS) {
        int b = tid / N_EXPERTS;
        int e = tid % N_EXPERTS;
        float l = 0.f;
        #pragma unroll
        for (int k = 0; k < NUM_FREQS; ++k)
            l += s_amp[b][k] * wg[k*N_EXPERTS + e];
        s_log[b][e] = l;
    }
    __syncthreads();

    if (tid < Bb) {
        int b = tid;
        int i1 = 0; float v1 = s_log[b][0];
        #pragma unroll
        for (int e = 1; e < N_EXPERTS; ++e)
            if (s_log[b][e] > v1) { v1 = s_log[b][e]; i1 = e; }
        int i2 = -1; float v2 = -INFINITY;
        #pragma unroll
        for (int e = 0; e < N_EXPERTS; ++e)
            if (e != i1 && s_log[b][e] > v2) { v2 = s_log[b][e]; i2 = e; }
        float e1 = expf(v2 - v1);
        float den = 1.f + e1;
        g_gates[b*2 + 0] = 1.f / den;
        g_gates[b*2 + 1] = e1 / den;
        g_eidx [b*2 + 0] = i1;
        g_eidx [b*2 + 1] = i2;
    }
}

// ---------------------------------------------------------------------------
// MoE: R9 champion (single-wave persistent, grid (32,4), B resident,
// A 64-wide k-chunks 2-stage, 256 threads, warp tile 64x32). Unchanged.
// ---------------------------------------------------------------------------
#define TILES_PER_CTA 6
#define NCHUNK (TILES_PER_CTA*2)          // 12 k-chunks
#define MASTR 72                           // A chunk row stride (elements)
#define MBSTR 136                          // B row stride (elements)
#define MSA(stage, hl) ((uint32_t)((stage)*36864 + (hl)*18432))
#define MSB_BASE 73728u
#define MSB(e, hl)     ((uint32_t)(MSB_BASE + ((e)*2+(hl))*34816))
#define MBIAS 212992u
#define MOE_SMEM 214016u

__device__ __forceinline__ void moe_loadA_chunk(uint32_t smb, int stage,
                                                int row0, int kc, int tid) {
    #pragma unroll
    for (int j = 0; j < 8; ++j) {
        int i  = tid + j*256;
        int hl = i >> 10;
        int rem = i & 1023;
        int r = rem >> 3, c = rem & 7;
        const __nv_bfloat16* src = (hl ? g_xLo : g_xHi)
                                 + (size_t)(row0 + r)*128 + kc*64 + c*8;
        uint32_t dst = smb + MSA(stage, hl) + (uint32_t)(r*MASTR + c*8)*2u;
        CP_ASYNC16(dst, src);
    }
    CP_COMMIT();
}

__global__ __launch_bounds__(256, 1)
void moe_mma_kernel(const float* __restrict__ eb,
                    float* __restrict__ out) {
    extern __shared__ char dsm[];
    const uint32_t smb = smem_u32(dsm);

    const int tid  = threadIdx.x;
    const int wid  = tid >> 5;
    const int lane = tid & 31;
    const int g    = lane >> 2;
    const int t    = lane & 3;
    const int warp_m = wid & 1;
    const int warp_n = wid >> 1;
    const int bb   = blockIdx.y;

    const int e0 = g_eidx[bb*2 + 0];
    const int e1 = g_eidx[bb*2 + 1];
    const float g0 = g_gates[bb*2 + 0];
    const float g1 = g_gates[bb*2 + 1];
    const int eArr[2] = {e0, e1};

    const int pmBase = bb*NPOS_PER_B + blockIdx.x * (128*TILES_PER_CTA);

    float* biasSm = (float*)(dsm + MBIAS);
    {
        int s = tid >> 7, f = tid & 127;
        biasSm[tid] = eb[eArr[s]*128 + f];
    }

    moe_loadA_chunk(smb, 0, pmBase, 0, tid);
    #pragma unroll
    for (int j = 0; j < 32; ++j) {
        int i  = tid + j*256;
        int buf = i >> 11;
        int rem = i & 2047;
        int n = rem >> 4, c = rem & 15;
        int e = buf >> 1, hl = buf & 1;
        const __nv_bfloat16* src = (hl ? g_wtLo : g_wtHi)
                                 + (size_t)eArr[e]*16384 + n*128 + c*8;
        uint32_t dst = smb + MSB(e, hl) + (uint32_t)(n*MBSTR + c*8)*2u;
        CP_ASYNC16(dst, src);
    }
    CP_COMMIT();
    moe_loadA_chunk(smb, 1, pmBase, 1, tid);

    float acc[2][4][4][4];

    for (int ci = 0; ci < NCHUNK; ++ci) {
        const int tile  = ci >> 1;
        const int kc    = ci & 1;
        const int stage = ci & 1;
        const int pm0   = pmBase + tile*128;

        if (ci < NCHUNK-1) { CP_WAIT(1); } else { CP_WAIT(0); }
        __syncthreads();

        if (kc == 0) {
            #pragma unroll
            for (int s = 0; s < 2; ++s)
                #pragma unroll
                for (int mt = 0; mt < 4; ++mt)
                    #pragma unroll
                    for (int nt = 0; nt < 4; ++nt)
                        #pragma unroll
                        for (int j = 0; j < 4; ++j) acc[s][mt][nt][j] = 0.f;
        }

        const __nv_bfloat16* Ahi = (const __nv_bfloat16*)(dsm + MSA(stage, 0));
        const __nv_bfloat16* Alo = (const __nv_bfloat16*)(dsm + MSA(stage, 1));
        const __nv_bfloat16* Bhi0 = (const __nv_bfloat16*)(dsm + MSB(0,0));
        const __nv_bfloat16* Blo0 = (const __nv_bfloat16*)(dsm + MSB(0,1));
        const __nv_bfloat16* Bhi1 = (const __nv_bfloat16*)(dsm + MSB(1,0));
        const __nv_bfloat16* Blo1 = (const __nv_bfloat16*)(dsm + MSB(1,1));

        #pragma unroll
        for (int ks = 0; ks < 4; ++ks) {
            const int k0 = ks*16;
            const int kg = kc*64 + k0;
            uint32_t a[2][4][4];
            #pragma unroll
            for (int mt = 0; mt < 4; ++mt) {
                int r0 = warp_m*64 + mt*16 + g;
                const __nv_bfloat16* apH = Ahi + k0 + 2*t;
                const __nv_bfloat16* apL = Alo + k0 + 2*t;
                a[0][mt][0] = *(const uint32_t*)(apH + (size_t)r0*MASTR);
                a[0][mt][1] = *(const uint32_t*)(apH + (size_t)(r0+8)*MASTR);
                a[0][mt][2] = *(const uint32_t*)(apH + (size_t)r0*MASTR + 8);
                a[0][mt][3] = *(const uint32_t*)(apH + (size_t)(r0+8)*MASTR + 8);
                a[1][mt][0] = *(const uint32_t*)(apL + (size_t)r0*MASTR);
                a[1][mt][1] = *(const uint32_t*)(apL + (size_t)(r0+8)*MASTR);
                a[1][mt][2] = *(const uint32_t*)(apL + (size_t)r0*MASTR + 8);
                a[1][mt][3] = *(const uint32_t*)(apL + (size_t)(r0+8)*MASTR + 8);
            }
            #pragma unroll
            for (int s = 0; s < 2; ++s) {
                const __nv_bfloat16* BH = s ? Bhi1 : Bhi0;
                const __nv_bfloat16* BL = s ? Blo1 : Blo0;
                uint32_t bfr[2][4][2];
                #pragma unroll
                for (int nt = 0; nt < 4; ++nt) {
                    int n = warp_n*32 + nt*8 + g;
                    const __nv_bfloat16* bpH = BH + (size_t)n*MBSTR + kg + 2*t;
                    const __nv_bfloat16* bpL = BL + (size_t)n*MBSTR + kg + 2*t;
                    bfr[0][nt][0] = *(const uint32_t*)bpH;
                    bfr[0][nt][1] = *(const uint32_t*)(bpH + 8);
                    bfr[1][nt][0] = *(const uint32_t*)bpL;
                    bfr[1][nt][1] = *(const uint32_t*)(bpL + 8);
                }
                #pragma unroll
                for (int mt = 0; mt < 4; ++mt)
                    #pragma unroll
                    for (int nt = 0; nt < 4; ++nt) {
                        mma16816(acc[s][mt][nt], a[0][mt], bfr[0][nt][0], bfr[0][nt][1]);
                        mma16816(acc[s][mt][nt], a[1][mt], bfr[0][nt][0], bfr[0][nt][1]);
                        mma16816(acc[s][mt][nt], a[0][mt], bfr[1][nt][0], bfr[1][nt][1]);
                    }
            }
        }
        __syncthreads();

        if (ci + 2 < NCHUNK) {
            int nci = ci + 2;
            moe_loadA_chunk(smb, nci & 1, pmBase + (nci >> 1)*128, nci & 1, tid);
        }

        if (kc == 1) {
            #pragma unroll
            for (int mt = 0; mt < 4; ++mt) {
                int row = pm0 + warp_m*64 + mt*16 + g;
                #pragma unroll
                for (int nt = 0; nt < 4; ++nt) {
                    int col0 = warp_n*32 + nt*8 + 2*t;
                    float b00 = biasSm[col0],       b01 = biasSm[col0 + 1];
                    float b10 = biasSm[128 + col0], b11 = biasSm[128 + col0 + 1];
                    float o[4];
                    #pragma unroll
                    for (int j = 0; j < 4; ++j) {
                        float v0 = acc[0][mt][nt][j] + ((j & 1) ? b01 : b00);
                        float v1 = acc[1][mt][nt][j] + ((j & 1) ? b11 : b10);
                        o[j] = v0 + __logf(g0 + g1 * __expf(v1 - v0));
                    }
                    *(float2*)&out[(size_t)row*128 + col0]     = make_float2(o[0], o[1]);
                    *(float2*)&out[(size_t)(row+8)*128 + col0] = make_float2(o[2], o[3]);
                }
            }
        }
    }
}

// ---------------------------------------------------------------------------
// Launch
// ---------------------------------------------------------------------------
extern "C" void kernel_launch(void* const* d_in, const int* in_sizes, int n_in,
                              void* d_out, int out_size) {
    const float* x        = (const float*)d_in[0];
    const float* conv_w   = (const float*)d_in[1];
    const float* conv_b   = (const float*)d_in[2];
    const float* bn_gamma = (const float*)d_in[3];
    const float* bn_beta  = (const float*)d_in[4];
    const float* bn_mean  = (const float*)d_in[5];
    const float* bn_var   = (const float*)d_in[6];
    const float* fuse_w   = (const float*)d_in[7];
    const float* fuse_b   = (const float*)d_in[8];
    const float* w_gate   = (const float*)d_in[9];
    const float* expert_w = (const float*)d_in[10];
    const float* expert_b = (const float*)d_in[11];
    float* out = (float*)d_out;

    __nv_bfloat16 *xHi, *xLo, *aHi0, *aLo0, *aHi1, *aLo1;
    cudaGetSymbolAddress((void**)&xHi,  g_xHi);
    cudaGetSymbolAddress((void**)&xLo,  g_xLo);
    cudaGetSymbolAddress((void**)&aHi0, g_aHi0);
    cudaGetSymbolAddress((void**)&aLo0, g_aLo0);
    cudaGetSymbolAddress((void**)&aHi1, g_aHi1);
    cudaGetSymbolAddress((void**)&aLo1, g_aLo1);

    cudaFuncSetAttribute(conv_mma_kernel,
                         cudaFuncAttributeMaxDynamicSharedMemorySize, CV_SMEM);
    cudaFuncSetAttribute(conv_mma_small,
                         cudaFuncAttributeMaxDynamicSharedMemorySize, CS_SMEM);
    cudaFuncSetAttribute(moe_mma_kernel,
                         cudaFuncAttributeMaxDynamicSharedMemorySize, MOE_SMEM);

    xsplit_kernel<<<(NPOS_TOTAL*32 + 255)/256, 256>>>((const float4*)x);
    cwsplit_kernel<<<(N_CONV*128*512 + 255)/256, 256>>>(conv_w);
    wsplit_kernel<<<(N_EXPERTS*128*128 + 255)/256, 256>>>(expert_w);

    const __nv_bfloat16* iH = xHi;
    const __nv_bfloat16* iL = xLo;
    int Si = 32;
    for (int l = 0; l < N_CONV; ++l) {
        int So = Si >> 1;
        int M  = 96 * So * So;
        __nv_bfloat16* oH = (l & 1) ? aHi1 : aHi0;
        __nv_bfloat16* oL = (l & 1) ? aLo1 : aLo0;
        if (l == 0) {
            conv_mma_kernel<<<(M + 63)/64, 256, CV_SMEM>>>(iH, iL, oH, oL, Si, So, M, l,
                                                           conv_b   + l*128,
                                                           bn_gamma + l*128,
                                                           bn_beta  + l*128,
                                                           bn_mean  + l*128,
                                                           bn_var   + l*128);
        } else {
            conv_mma_small<<<(M + 15)/16, 256, CS_SMEM>>>(iH, iL, oH, oL, Si, So, M, l,
                                                          conv_b   + l*128,
                                                          bn_gamma + l*128,
                                                          bn_beta  + l*128,
                                                          bn_mean  + l*128,
                                                          bn_var   + l*128);
        }
        iH = oH; iL = oL;
        Si = So;
    }

    gates_kernel<<<1, 128>>>(aHi0, aLo0, fuse_w, fuse_b, w_gate);

    dim3 moeGrid(32, Bb);
    moe_mma_kernel<<<moeGrid, 256, MOE_SMEM>>>(expert_b, out);
}

// round 15
// speedup vs baseline: 1.1401x; 1.0374x over previous
#include <cuda_runtime.h>
#include <cuda_bf16.h>
#include <math.h>
#include <stdint.h>

// ---------------------------------------------------------------------------
// Problem constants
// ---------------------------------------------------------------------------
#define Bb 4
#define Tt 24
#define Hh 32
#define Ww 32
#define Dd 128
#define NPOS_PER_B (Tt*Hh*Ww)        // 24576
#define NPOS_TOTAL (Bb*NPOS_PER_B)   // 98304
#define N_CONV 5
#define NUM_FREQS 12
#define N_EXPERTS 7
#define BN_EPS 1e-5f
#define COMBINE_EPS 2.220446049250313e-16f

// ---------------------------------------------------------------------------
// Device scratch
// ---------------------------------------------------------------------------
__device__ __align__(16) __nv_bfloat16 g_xHi[NPOS_TOTAL*128];
__device__ __align__(16) __nv_bfloat16 g_xLo[NPOS_TOTAL*128];
__device__ __align__(16) __nv_bfloat16 g_aHi0[24576*128];
__device__ __align__(16) __nv_bfloat16 g_aLo0[24576*128];
__device__ __align__(16) __nv_bfloat16 g_aHi1[6144*128];
__device__ __align__(16) __nv_bfloat16 g_aLo1[6144*128];
__device__ __align__(16) __nv_bfloat16 g_cwHi[N_CONV*128*512];   // [l][co][k]
__device__ __align__(16) __nv_bfloat16 g_cwLo[N_CONV*128*512];
__device__ float g_gates[Bb*2];
__device__ int   g_eidx [Bb*2];
__device__ __align__(16) __nv_bfloat16 g_wtHi[N_EXPERTS*128*128]; // [e][f][d]
__device__ __align__(16) __nv_bfloat16 g_wtLo[N_EXPERTS*128*128];

__device__ __forceinline__ uint32_t pack_bf16(float a, float b) {
    uint32_t lo = (uint32_t)__bfloat16_as_ushort(__float2bfloat16(a));
    uint32_t hi = (uint32_t)__bfloat16_as_ushort(__float2bfloat16(b));
    return lo | (hi << 16);
}
__device__ __forceinline__ uint32_t smem_u32(const void* p) {
    uint32_t a;
    asm("{ .reg .u64 t; cvta.to.shared.u64 t, %1; cvt.u32.u64 %0, t; }"
        : "=r"(a) : "l"(p));
    return a;
}

// mma.sync m16n8k16 bf16
__device__ __forceinline__ void mma16816(float* d, const uint32_t* a,
                                         uint32_t b0, uint32_t b1) {
    asm volatile(
        "mma.sync.aligned.m16n8k16.row.col.f32.bf16.bf16.f32 "
        "{%0,%1,%2,%3}, {%4,%5,%6,%7}, {%8,%9}, {%0,%1,%2,%3};"
        : "+f"(d[0]), "+f"(d[1]), "+f"(d[2]), "+f"(d[3])
        : "r"(a[0]), "r"(a[1]), "r"(a[2]), "r"(a[3]), "r"(b0), "r"(b1));
}

#define CP_ASYNC16(dst, src) \
    asm volatile("cp.async.cg.shared.global [%0], [%1], 16;" :: "r"(dst), "l"(src))
#define CP_COMMIT() asm volatile("cp.async.commit_group;")
#define CP_WAIT(N)  asm volatile("cp.async.wait_group %0;" :: "n"(N))

// ---------------------------------------------------------------------------
// Merged prologue: x split + conv weight split/transpose + expert weight
// split/transpose in ONE kernel.
// ---------------------------------------------------------------------------
#define T1 (NPOS_TOTAL*32)           // x float4 count
#define T2 (N_CONV*128*512)          // conv weight elems
#define T3 (N_EXPERTS*128*128)       // expert weight elems

__global__ void prologue_split_kernel(const float4* __restrict__ x,
                                      const float* __restrict__ cw,
                                      const float* __restrict__ ew) {
    int idx = blockIdx.x * 256 + threadIdx.x;
    if (idx < T1) {
        float4 v = x[idx];
        __nv_bfloat16 hx = __float2bfloat16(v.x);
        __nv_bfloat16 hy = __float2bfloat16(v.y);
        __nv_bfloat16 hz = __float2bfloat16(v.z);
        __nv_bfloat16 hw = __float2bfloat16(v.w);
        uint2 h = make_uint2(
            (uint32_t)__bfloat16_as_ushort(hx) | ((uint32_t)__bfloat16_as_ushort(hy) << 16),
            (uint32_t)__bfloat16_as_ushort(hz) | ((uint32_t)__bfloat16_as_ushort(hw) << 16));
        uint2 l = make_uint2(
            pack_bf16(v.x - __bfloat162float(hx), v.y - __bfloat162float(hy)),
            pack_bf16(v.z - __bfloat162float(hz), v.w - __bfloat162float(hw)));
        ((uint2*)g_xHi)[idx] = h;
        ((uint2*)g_xLo)[idx] = l;
    } else if (idx < T1 + T2) {
        int i = idx - T1;
        int l   = i / (128*512);
        int rem = i - l*128*512;
        int k   = rem & 511;
        int tap = k >> 7;
        int ci  = k & 127;
        int co  = rem >> 9;
        float v = cw[((l*128 + co)*128 + ci)*4 + tap];
        __nv_bfloat16 h = __float2bfloat16(v);
        g_cwHi[i] = h;
        g_cwLo[i] = __float2bfloat16(v - __bfloat162float(h));
    } else if (idx < T1 + T2 + T3) {
        int i = idx - T1 - T2;
        int e = i / 16384;
        int rem = i - e*16384;
        int d = rem >> 7;
        int f = rem & 127;
        float v = ew[i];
        __nv_bfloat16 h = __float2bfloat16(v);
        g_wtHi[e*16384 + f*128 + d] = h;
        g_wtLo[e*16384 + f*128 + d] = __float2bfloat16(v - __bfloat162float(h));
    }
}

// ---------------------------------------------------------------------------
// Conv layer 1: BM=64 (champion, unchanged).
// ---------------------------------------------------------------------------
#define STR2 72    // 144 bytes/row
#define CV_A(db, hl)  ((uint32_t)(((db)*2+(hl)) * 9216))
#define CV_B(db, hl)  ((uint32_t)(36864 + ((db)*2+(hl)) * 18432))
#define CV_ROWOFF     110592u
#define CV_BN         111616u
#define CV_SMEM       112640u

__device__ __forceinline__ void conv_issue_chunk(
    uint32_t smb, char* dsm, int db, int chunk,
    const __nv_bfloat16* __restrict__ inHi,
    const __nv_bfloat16* __restrict__ inLo,
    int l, int tid)
{
    const int tap = chunk >> 1;
    const int ciB = (chunk & 1) * 64;
    const int* rowOffS = (const int*)(dsm + CV_ROWOFF);
    #pragma unroll
    for (int j = 0; j < 4; ++j) {
        int i   = tid + j*256;
        int buf = i >> 9;
        int rem = i & 511;
        int r   = rem >> 3, c8 = rem & 7;
        const __nv_bfloat16* src = (buf ? inLo : inHi) + rowOffS[r*4 + tap] + ciB + c8*8;
        uint32_t dst = smb + CV_A(db, buf) + (uint32_t)(r*STR2 + c8*8)*2u;
        CP_ASYNC16(dst, src);
    }
    #pragma unroll
    for (int j = 0; j < 8; ++j) {
        int i   = tid + j*256;
        int buf = i >> 10;
        int rem = i & 1023;
        int n   = rem >> 3, c8 = rem & 7;
        const __nv_bfloat16* src = (buf ? g_cwLo : g_cwHi)
                                 + (size_t)(l*128 + n)*512 + chunk*64 + c8*8;
        uint32_t dst = smb + CV_B(db, buf) + (uint32_t)(n*STR2 + c8*8)*2u;
        CP_ASYNC16(dst, src);
    }
    CP_COMMIT();
}

__global__ __launch_bounds__(256)
void conv_mma_kernel(const __nv_bfloat16* __restrict__ inHi,
                     const __nv_bfloat16* __restrict__ inLo,
                     __nv_bfloat16* __restrict__ outHi,
                     __nv_bfloat16* __restrict__ outLo,
                     int Si, int So, int M, int l,
                     const float* __restrict__ cb,
                     const float* __restrict__ gma,
                     const float* __restrict__ bta,
                     const float* __restrict__ mu,
                     const float* __restrict__ var) {
    extern __shared__ char dsm[];
    const uint32_t smb = smem_u32(dsm);

    const int tid  = threadIdx.x;
    const int wid  = tid >> 5;
    const int lane = tid & 31;
    const int g    = lane >> 2;
    const int t    = lane & 3;
    const int warp_m = wid & 1;
    const int warp_n = wid >> 1;
    const int pm0  = blockIdx.x * 64;

    int*   rowOffS = (int*)(dsm + CV_ROWOFF);
    float* aCs     = (float*)(dsm + CV_BN);
    float* cCs     = aCs + 128;

    {
        int r = tid >> 2, tap = tid & 3;
        int p = pm0 + r; if (p > M-1) p = M-1;
        int sq = So * So;
        int n  = p / sq;
        int rm = p - n*sq;
        int y  = rm / So;
        int xx = rm - y*So;
        int ky = tap >> 1, kx = tap & 1;
        rowOffS[r*4 + tap] = ((n*Si + 2*y + ky)*Si + (2*xx + kx)) * 128;
    }
    if (tid < 128) {
        float a = gma[tid] * rsqrtf(var[tid] + BN_EPS);
        aCs[tid] = a;
        cCs[tid] = a * (cb[tid] - mu[tid]) + bta[tid];
    }
    __syncthreads();

    conv_issue_chunk(smb, dsm, 0, 0, inHi, inLo, l, tid);

    float acc[2][4][4];
    #pragma unroll
    for (int mt = 0; mt < 2; ++mt)
        #pragma unroll
        for (int nt = 0; nt < 4; ++nt)
            #pragma unroll
            for (int j = 0; j < 4; ++j) acc[mt][nt][j] = 0.f;

    for (int c = 0; c < 8; ++c) {
        if (c < 7) {
            conv_issue_chunk(smb, dsm, (c+1)&1, c+1, inHi, inLo, l, tid);
            CP_WAIT(1);
        } else {
            CP_WAIT(0);
        }
        __syncthreads();

        const int db = c & 1;
        const __nv_bfloat16* Ahi = (const __nv_bfloat16*)(dsm + CV_A(db,0));
        const __nv_bfloat16* Alo = (const __nv_bfloat16*)(dsm + CV_A(db,1));
        const __nv_bfloat16* Bhi = (const __nv_bfloat16*)(dsm + CV_B(db,0));
        const __nv_bfloat16* Blo = (const __nv_bfloat16*)(dsm + CV_B(db,1));

        #pragma unroll
        for (int term = 0; term < 3; ++term) {
            const __nv_bfloat16* Ab = (term == 1) ? Alo : Ahi;
            const __nv_bfloat16* Bf = (term == 2) ? Blo : Bhi;
            #pragma unroll
            for (int ks = 0; ks < 4; ++ks) {
                const int k0 = ks*16;
                uint32_t af[2][4];
                #pragma unroll
                for (int mt = 0; mt < 2; ++mt) {
                    int r0 = warp_m*32 + mt*16 + g;
                    const __nv_bfloat16* ap = Ab + k0 + 2*t;
                    af[mt][0] = *(const uint32_t*)(ap + (size_t)r0*STR2);
                    af[mt][1] = *(const uint32_t*)(ap + (size_t)(r0+8)*STR2);
                    af[mt][2] = *(const uint32_t*)(ap + (size_t)r0*STR2 + 8);
                    af[mt][3] = *(const uint32_t*)(ap + (size_t)(r0+8)*STR2 + 8);
                }
                #pragma unroll
                for (int nt = 0; nt < 4; ++nt) {
                    int n = warp_n*32 + nt*8 + g;
                    const __nv_bfloat16* bp = Bf + (size_t)n*STR2 + k0 + 2*t;
                    uint32_t b0 = *(const uint32_t*)bp;
                    uint32_t b1 = *(const uint32_t*)(bp + 8);
                    mma16816(acc[0][nt], af[0], b0, b1);
                    mma16816(acc[1][nt], af[1], b0, b1);
                }
            }
        }
        __syncthreads();
    }

    uint32_t* oHi = (uint32_t*)outHi;
    uint32_t* oLo = (uint32_t*)outLo;
    #pragma unroll
    for (int mt = 0; mt < 2; ++mt) {
        int r0 = pm0 + warp_m*32 + mt*16 + g;
        #pragma unroll
        for (int nt = 0; nt < 4; ++nt) {
            int col = warp_n*32 + nt*8 + 2*t;
            float a0 = aCs[col], a1 = aCs[col+1];
            float c0 = cCs[col], c1 = cCs[col+1];
            float v00 = acc[mt][nt][0]*a0 + c0; v00 = v00 > 0.f ? v00 : 0.2f*v00;
            float v01 = acc[mt][nt][1]*a1 + c1; v01 = v01 > 0.f ? v01 : 0.2f*v01;
            float v10 = acc[mt][nt][2]*a0 + c0; v10 = v10 > 0.f ? v10 : 0.2f*v10;
            float v11 = acc[mt][nt][3]*a1 + c1; v11 = v11 > 0.f ? v11 : 0.2f*v11;
            if (r0 < M) {
                __nv_bfloat16 h0 = __float2bfloat16(v00);
                __nv_bfloat16 h1 = __float2bfloat16(v01);
                uint32_t hw = (uint32_t)__bfloat16_as_ushort(h0)
                            | ((uint32_t)__bfloat16_as_ushort(h1) << 16);
                uint32_t lw = pack_bf16(v00 - __bfloat162float(h0),
                                        v01 - __bfloat162float(h1));
                oHi[r0*64 + (col>>1)] = hw;
                oLo[r0*64 + (col>>1)] = lw;
            }
            if (r0 + 8 < M) {
                __nv_bfloat16 h0 = __float2bfloat16(v10);
                __nv_bfloat16 h1 = __float2bfloat16(v11);
                uint32_t hw = (uint32_t)__bfloat16_as_ushort(h0)
                            | ((uint32_t)__bfloat16_as_ushort(h1) << 16);
                uint32_t lw = pack_bf16(v10 - __bfloat162float(h0),
                                        v11 - __bfloat162float(h1));
                oHi[(r0+8)*64 + (col>>1)] = hw;
                oLo[(r0+8)*64 + (col>>1)] = lw;
            }
        }
    }
}

// ---------------------------------------------------------------------------
// Conv layers 2-3: BM=16 pipelined (R14 champion, unchanged).
// ---------------------------------------------------------------------------
#define CS_STG 41472u
#define CS_A(db, hl) ((uint32_t)((db)*CS_STG + (hl)*2304u))
#define CS_B(db, hl) ((uint32_t)((db)*CS_STG + 4608u + (hl)*18432u))
#define CS_ROWOFF 82944u
#define CS_BN     83200u
#define CS_SMEM   84224u

__device__ __forceinline__ void convs_issue_chunk(
    uint32_t smb, char* dsm, int db, int chunk,
    const __nv_bfloat16* __restrict__ inHi,
    const __nv_bfloat16* __restrict__ inLo,
    int l, int tid)
{
    const int tap = chunk >> 1;
    const int ciB = (chunk & 1) * 64;
    const int* rowOffS = (const int*)(dsm + CS_ROWOFF);
    {
        int i   = tid;
        int buf = i >> 7;
        int rem = i & 127;
        int r   = rem >> 3, c8 = rem & 7;
        const __nv_bfloat16* src = (buf ? inLo : inHi) + rowOffS[r*4 + tap] + ciB + c8*8;
        uint32_t dst = smb + CS_A(db, buf) + (uint32_t)(r*STR2 + c8*8)*2u;
        CP_ASYNC16(dst, src);
    }
    #pragma unroll
    for (int j = 0; j < 8; ++j) {
        int i   = tid + j*256;
        int buf = i >> 10;
        int rem = i & 1023;
        int n   = rem >> 3, c8 = rem & 7;
        const __nv_bfloat16* src = (buf ? g_cwLo : g_cwHi)
                                 + (size_t)(l*128 + n)*512 + chunk*64 + c8*8;
        uint32_t dst = smb + CS_B(db, buf) + (uint32_t)(n*STR2 + c8*8)*2u;
        CP_ASYNC16(dst, src);
    }
    CP_COMMIT();
}

__global__ __launch_bounds__(256)
void conv_mma_small(const __nv_bfloat16* __restrict__ inHi,
                    const __nv_bfloat16* __restrict__ inLo,
                    __nv_bfloat16* __restrict__ outHi,
                    __nv_bfloat16* __restrict__ outLo,
                    int Si, int So, int M, int l,
                    const float* __restrict__ cb,
                    const float* __restrict__ gma,
                    const float* __restrict__ bta,
                    const float* __restrict__ mu,
                    const float* __restrict__ var) {
    extern __shared__ char dsm[];
    const uint32_t smb = smem_u32(dsm);

    const int tid  = threadIdx.x;
    const int wid  = tid >> 5;
    const int lane = tid & 31;
    const int g    = lane >> 2;
    const int t    = lane & 3;
    const int pm0  = blockIdx.x * 16;

    int*   rowOffS = (int*)(dsm + CS_ROWOFF);
    float* aCs     = (float*)(dsm + CS_BN);
    float* cCs     = aCs + 128;

    if (tid < 64) {
        int r = tid >> 2, tap = tid & 3;
        int p = pm0 + r; if (p > M-1) p = M-1;
        int sq = So * So;
        int n  = p / sq;
        int rm = p - n*sq;
        int y  = rm / So;
        int xx = rm - y*So;
        int ky = tap >> 1, kx = tap & 1;
        rowOffS[r*4 + tap] = ((n*Si + 2*y + ky)*Si + (2*xx + kx)) * 128;
    }
    if (tid < 128) {
        float a = gma[tid] * rsqrtf(var[tid] + BN_EPS);
        aCs[tid] = a;
        cCs[tid] = a * (cb[tid] - mu[tid]) + bta[tid];
    }
    __syncthreads();

    convs_issue_chunk(smb, dsm, 0, 0, inHi, inLo, l, tid);

    float acc[2][4];
    #pragma unroll
    for (int nt = 0; nt < 2; ++nt)
        #pragma unroll
        for (int j = 0; j < 4; ++j) acc[nt][j] = 0.f;

    for (int c = 0; c < 8; ++c) {
        if (c < 7) {
            convs_issue_chunk(smb, dsm, (c+1)&1, c+1, inHi, inLo, l, tid);
            CP_WAIT(1);
        } else {
            CP_WAIT(0);
        }
        __syncthreads();

        const int db = c & 1;
        const __nv_bfloat16* Ahi = (const __nv_bfloat16*)(dsm + CS_A(db,0));
        const __nv_bfloat16* Alo = (const __nv_bfloat16*)(dsm + CS_A(db,1));
        const __nv_bfloat16* Bhi = (const __nv_bfloat16*)(dsm + CS_B(db,0));
        const __nv_bfloat16* Blo = (const __nv_bfloat16*)(dsm + CS_B(db,1));

        #pragma unroll
        for (int term = 0; term < 3; ++term) {
            const __nv_bfloat16* Ab = (term == 1) ? Alo : Ahi;
            const __nv_bfloat16* Bf = (term == 2) ? Blo : Bhi;
            #pragma unroll
            for (int ks = 0; ks < 4; ++ks) {
                const int k0 = ks*16;
                uint32_t af[4];
                const __nv_bfloat16* ap = Ab + k0 + 2*t;
                af[0] = *(const uint32_t*)(ap + (size_t)g*STR2);
                af[1] = *(const uint32_t*)(ap + (size_t)(g+8)*STR2);
                af[2] = *(const uint32_t*)(ap + (size_t)g*STR2 + 8);
                af[3] = *(const uint32_t*)(ap + (size_t)(g+8)*STR2 + 8);
                #pragma unroll
                for (int nt = 0; nt < 2; ++nt) {
                    int n = wid*16 + nt*8 + g;
                    const __nv_bfloat16* bp = Bf + (size_t)n*STR2 + k0 + 2*t;
                    uint32_t b0 = *(const uint32_t*)bp;
                    uint32_t b1 = *(const uint32_t*)(bp + 8);
                    mma16816(acc[nt], af, b0, b1);
                }
            }
        }
        __syncthreads();
    }

    uint32_t* oHi = (uint32_t*)outHi;
    uint32_t* oLo = (uint32_t*)outLo;
    {
        int r0 = pm0 + g;
        #pragma unroll
        for (int nt = 0; nt < 2; ++nt) {
            int col = wid*16 + nt*8 + 2*t;
            float a0 = aCs[col], a1 = aCs[col+1];
            float c0 = cCs[col], c1 = cCs[col+1];
            float v00 = acc[nt][0]*a0 + c0; v00 = v00 > 0.f ? v00 : 0.2f*v00;
            float v01 = acc[nt][1]*a1 + c1; v01 = v01 > 0.f ? v01 : 0.2f*v01;
            float v10 = acc[nt][2]*a0 + c0; v10 = v10 > 0.f ? v10 : 0.2f*v10;
            float v11 = acc[nt][3]*a1 + c1; v11 = v11 > 0.f ? v11 : 0.2f*v11;
            {
                __nv_bfloat16 h0 = __float2bfloat16(v00);
                __nv_bfloat16 h1 = __float2bfloat16(v01);
                uint32_t hw = (uint32_t)__bfloat16_as_ushort(h0)
                            | ((uint32_t)__bfloat16_as_ushort(h1) << 16);
                uint32_t lw = pack_bf16(v00 - __bfloat162float(h0),
                                        v01 - __bfloat162float(h1));
                oHi[r0*64 + (col>>1)] = hw;
                oLo[r0*64 + (col>>1)] = lw;
            }
            {
                __nv_bfloat16 h0 = __float2bfloat16(v10);
                __nv_bfloat16 h1 = __float2bfloat16(v11);
                uint32_t hw = (uint32_t)__bfloat16_as_ushort(h0)
                            | ((uint32_t)__bfloat16_as_ushort(h1) << 16);
                uint32_t lw = pack_bf16(v10 - __bfloat162float(h0),
                                        v11 - __bfloat162float(h1));
                oHi[(r0+8)*64 + (col>>1)] = hw;
                oLo[(r0+8)*64 + (col>>1)] = lw;
            }
        }
    }
}

// ---------------------------------------------------------------------------
// Conv layers 4-5 (tiny M): full-K resident, ONE cp.async batch + ONE
// barrier, zero pipeline depth. CTA = 16 rows x 64 cols (n-split).
// A: [hl][16][STR3], B: [hl][64][STR3], STR3=520 elems.
// ---------------------------------------------------------------------------
#define STR3 520
#define CF_A(hl) ((uint32_t)((hl) * 16640u))          // 16*520*2
#define CF_B(hl) ((uint32_t)(33280u + (hl) * 66560u)) // 64*520*2
#define CF_ROWOFF 166400u
#define CF_BN     166912u
#define CF_SMEM   168448u

__global__ __launch_bounds__(256)
void conv_mma_fullk(const __nv_bfloat16* __restrict__ inHi,
                    const __nv_bfloat16* __restrict__ inLo,
                    __nv_bfloat16* __restrict__ outHi,
                    __nv_bfloat16* __restrict__ outLo,
                    int Si, int So, int M, int l,
                    const float* __restrict__ cb,
                    const float* __restrict__ gma,
                    const float* __restrict__ bta,
                    const float* __restrict__ mu,
                    const float* __restrict__ var) {
    extern __shared__ char dsm[];
    const uint32_t smb = smem_u32(dsm);

    const int tid  = threadIdx.x;
    const int wid  = tid >> 5;          // 8 warps -> 8 col groups of 8
    const int lane = tid & 31;
    const int g    = lane >> 2;
    const int t    = lane & 3;
    const int rt0  = blockIdx.x >> 1;   // row tile
    const int nh   = blockIdx.x & 1;    // n-half
    const int pm0  = rt0 * 16;

    int*   rowOffS = (int*)(dsm + CF_ROWOFF);
    float* aCs     = (float*)(dsm + CF_BN);
    float* cCs     = aCs + 128;

    if (tid < 64) {
        int r = tid >> 2, tap = tid & 3;
        int p = pm0 + r; if (p > M-1) p = M-1;
        int sq = So * So;
        int n  = p / sq;
        int rm = p - n*sq;
        int y  = rm / So;
        int xx = rm - y*So;
        int ky = tap >> 1, kx = tap & 1;
        rowOffS[r*4 + tap] = ((n*Si + 2*y + ky)*Si + (2*xx + kx)) * 128;
    }
    if (tid < 128) {
        float a = gma[tid] * rsqrtf(var[tid] + BN_EPS);
        aCs[tid] = a;
        cCs[tid] = a * (cb[tid] - mu[tid]) + bta[tid];
    }
    __syncthreads();

    // A full-K: 2048 uint4 (hl x 16 rows x 64 uint4-of-8)
    #pragma unroll
    for (int j = 0; j < 8; ++j) {
        int i  = tid + j*256;
        int hl = i >> 10;
        int rem = i & 1023;
        int r = rem >> 6, c = rem & 63;   // k = c*8
        int tap = c >> 4, ci = (c & 15)*8;
        const __nv_bfloat16* src = (hl ? inLo : inHi) + rowOffS[r*4 + tap] + ci;
        uint32_t dst = smb + CF_A(hl) + (uint32_t)(r*STR3 + c*8)*2u;
        CP_ASYNC16(dst, src);
    }
    // B full-K: 8192 uint4 (hl x 64 n x 64)
    #pragma unroll
    for (int j = 0; j < 32; ++j) {
        int i  = tid + j*256;
        int hl = i >> 12;
        int rem = i & 4095;
        int n = rem >> 6, c = rem & 63;
        const __nv_bfloat16* src = (hl ? g_cwLo : g_cwHi)
                                 + (size_t)(l*128 + nh*64 + n)*512 + c*8;
        uint32_t dst = smb + CF_B(hl) + (uint32_t)(n*STR3 + c*8)*2u;
        CP_ASYNC16(dst, src);
    }
    CP_COMMIT();
    CP_WAIT(0);
    __syncthreads();

    const __nv_bfloat16* Ahi = (const __nv_bfloat16*)(dsm + CF_A(0));
    const __nv_bfloat16* Alo = (const __nv_bfloat16*)(dsm + CF_A(1));
    const __nv_bfloat16* Bhi = (const __nv_bfloat16*)(dsm + CF_B(0));
    const __nv_bfloat16* Blo = (const __nv_bfloat16*)(dsm + CF_B(1));

    float acc[4];
    acc[0] = acc[1] = acc[2] = acc[3] = 0.f;

    #pragma unroll
    for (int term = 0; term < 3; ++term) {
        const __nv_bfloat16* Ab = (term == 1) ? Alo : Ahi;
        const __nv_bfloat16* Bf = (term == 2) ? Blo : Bhi;
        for (int ks = 0; ks < 32; ++ks) {
            const int k0 = ks*16;
            uint32_t af[4];
            const __nv_bfloat16* ap = Ab + k0 + 2*t;
            af[0] = *(const uint32_t*)(ap + (size_t)g*STR3);
            af[1] = *(const uint32_t*)(ap + (size_t)(g+8)*STR3);
            af[2] = *(const uint32_t*)(ap + (size_t)g*STR3 + 8);
            af[3] = *(const uint32_t*)(ap + (size_t)(g+8)*STR3 + 8);
            int n = wid*8 + g;
            const __nv_bfloat16* bp = Bf + (size_t)n*STR3 + k0 + 2*t;
            uint32_t b0 = *(const uint32_t*)bp;
            uint32_t b1 = *(const uint32_t*)(bp + 8);
            mma16816(acc, af, b0, b1);
        }
    }

    uint32_t* oHi = (uint32_t*)outHi;
    uint32_t* oLo = (uint32_t*)outLo;
    {
        int r0 = pm0 + g;
        int col = nh*64 + wid*8 + 2*t;
        float a0 = aCs[col], a1 = aCs[col+1];
        float c0 = cCs[col], c1 = cCs[col+1];
        float v00 = acc[0]*a0 + c0; v00 = v00 > 0.f ? v00 : 0.2f*v00;
        float v01 = acc[1]*a1 + c1; v01 = v01 > 0.f ? v01 : 0.2f*v01;
        float v10 = acc[2]*a0 + c0; v10 = v10 > 0.f ? v10 : 0.2f*v10;
        float v11 = acc[3]*a1 + c1; v11 = v11 > 0.f ? v11 : 0.2f*v11;
        {
            __nv_bfloat16 h0 = __float2bfloat16(v00);
            __nv_bfloat16 h1 = __float2bfloat16(v01);
            uint32_t hw = (uint32_t)__bfloat16_as_ushort(h0)
                        | ((uint32_t)__bfloat16_as_ushort(h1) << 16);
            uint32_t lw = pack_bf16(v00 - __bfloat162float(h0),
                                    v01 - __bfloat162float(h1));
            oHi[r0*64 + (col>>1)] = hw;
            oLo[r0*64 + (col>>1)] = lw;
        }
        {
            __nv_bfloat16 h0 = __float2bfloat16(v10);
            __nv_bfloat16 h1 = __float2bfloat16(v11);
            uint32_t hw = (uint32_t)__bfloat16_as_ushort(h0)
                        | ((uint32_t)__bfloat16_as_ushort(h1) << 16);
            uint32_t lw = pack_bf16(v10 - __bfloat162float(h0),
                                    v11 - __bfloat162float(h1));
            oHi[(r0+8)*64 + (col>>1)] = hw;
            oLo[(r0+8)*64 + (col>>1)] = lw;
        }
    }
}

// ---------------------------------------------------------------------------
// Gates kernel
// ---------------------------------------------------------------------------
__global__ void gates_kernel(const __nv_bfloat16* __restrict__ zfHi,
                             const __nv_bfloat16* __restrict__ zfLo,
                             const float* __restrict__ fw,
                             const float* __restrict__ fb,
                             const float* __restrict__ wg) {
    __shared__ float s_s[96];
    __shared__ float s_amp[Bb][NUM_FREQS];
    __shared__ float s_log[Bb][N_EXPERTS];

    const int tid  = threadIdx.x;
    const int lane = tid & 31;
    const int warp = tid >> 5;

    for (int r = warp; r < 96; r += 4) {
        float v = 0.f;
        #pragma unroll
        for (int j = 0; j < 4; ++j) {
            int c = lane + j*32;
            float z = __bfloat162float(zfHi[r*128 + c]) + __bfloat162float(zfLo[r*128 + c]);
            v += z * fw[c];
        }
        #pragma unroll
        for (int off = 16; off; off >>= 1)
            v += __shfl_down_sync(0xffffffffu, v, off);
        if (lane == 0) s_s[r] = v + fb[0];
    }
    __syncthreads();

    if (tid < Bb*NUM_FREQS) {
        int b = tid / NUM_FREQS;
        int k = tid % NUM_FREQS + 1;
        float re = 0.f, im = 0.f;
        #pragma unroll
        for (int t = 0; t < Tt; ++t) {
            int m = (k * t) % 24;
            float ang = -(float)M_PI * (float)m / 12.f;
            float sv, cv;
            sincosf(ang, &sv, &cv);
            float x = s_s[b*Tt + t];
            re += x * cv;
            im += x * sv;
        }
        s_amp[b][k-1] = sqrtf(re*re + im*im) * 0.2041241452319315f;
    }
    __syncthreads();

    if (tid < Bb*N_EXPERTS) {
        int b = tid / N_EXPERTS;
        int e = tid % N_EXPERTS;
        float l = 0.f;
        #pragma unroll
        for (int k = 0; k < NUM_FREQS; ++k)
            l += s_amp[b][k] * wg[k*N_EXPERTS + e];
        s_log[b][e] = l;
    }
    __syncthreads();

    if (tid < Bb) {
        int b = tid;
        int i1 = 0; float v1 = s_log[b][0];
        #pragma unroll
        for (int e = 1; e < N_EXPERTS; ++e)
            if (s_log[b][e] > v1) { v1 = s_log[b][e]; i1 = e; }
        int i2 = -1; float v2 = -INFINITY;
        #pragma unroll
        for (int e = 0; e < N_EXPERTS; ++e)
            if (e != i1 && s_log[b][e] > v2) { v2 = s_log[b][e]; i2 = e; }
        float e1 = expf(v2 - v1);
        float den = 1.f + e1;
        g_gates[b*2 + 0] = 1.f / den;
        g_gates[b*2 + 1] = e1 / den;
        g_eidx [b*2 + 0] = i1;
        g_eidx [b*2 + 1] = i2;
    }
}

// ---------------------------------------------------------------------------
// MoE: R9/R14 champion (unchanged).
// ---------------------------------------------------------------------------
#define TILES_PER_CTA 6
#define NCHUNK (TILES_PER_CTA*2)
#define MASTR 72
#define MBSTR 136
#define MSA(stage, hl) ((uint32_t)((stage)*36864 + (hl)*18432))
#define MSB_BASE 73728u
#define MSB(e, hl)     ((uint32_t)(MSB_BASE + ((e)*2+(hl))*34816))
#define MBIAS 212992u
#define MOE_SMEM 214016u

__device__ __forceinline__ void moe_loadA_chunk(uint32_t smb, int stage,
                                                int row0, int kc, int tid) {
    #pragma unroll
    for (int j = 0; j < 8; ++j) {
        int i  = tid + j*256;
        int hl = i >> 10;
        int rem = i & 1023;
        int r = rem >> 3, c = rem & 7;
        const __nv_bfloat16* src = (hl ? g_xLo : g_xHi)
                                 + (size_t)(row0 + r)*128 + kc*64 + c*8;
        uint32_t dst = smb + MSA(stage, hl) + (uint32_t)(r*MASTR + c*8)*2u;
        CP_ASYNC16(dst, src);
    }
    CP_COMMIT();
}

__global__ __launch_bounds__(256, 1)
void moe_mma_kernel(const float* __restrict__ eb,
                    float* __restrict__ out) {
    extern __shared__ char dsm[];
    const uint32_t smb = smem_u32(dsm);

    const int tid  = threadIdx.x;
    const int wid  = tid >> 5;
    const int lane = tid & 31;
    const int g    = lane >> 2;
    const int t    = lane & 3;
    const int warp_m = wid & 1;
    const int warp_n = wid >> 1;
    const int bb   = blockIdx.y;

    const int e0 = g_eidx[bb*2 + 0];
    const int e1 = g_eidx[bb*2 + 1];
    const float g0 = g_gates[bb*2 + 0];
    const float g1 = g_gates[bb*2 + 1];
    const int eArr[2] = {e0, e1};

    const int pmBase = bb*NPOS_PER_B + blockIdx.x * (128*TILES_PER_CTA);

    float* biasSm = (float*)(dsm + MBIAS);
    {
        int s = tid >> 7, f = tid & 127;
        biasSm[tid] = eb[eArr[s]*128 + f];
    }

    moe_loadA_chunk(smb, 0, pmBase, 0, tid);
    #pragma unroll
    for (int j = 0; j < 32; ++j) {
        int i  = tid + j*256;
        int buf = i >> 11;
        int rem = i & 2047;
        int n = rem >> 4, c = rem & 15;
        int e = buf >> 1, hl = buf & 1;
        const __nv_bfloat16* src = (hl ? g_wtLo : g_wtHi)
                                 + (size_t)eArr[e]*16384 + n*128 + c*8;
        uint32_t dst = smb + MSB(e, hl) + (uint32_t)(n*MBSTR + c*8)*2u;
        CP_ASYNC16(dst, src);
    }
    CP_COMMIT();
    moe_loadA_chunk(smb, 1, pmBase, 1, tid);

    float acc[2][4][4][4];

    for (int ci = 0; ci < NCHUNK; ++ci) {
        const int tile  = ci >> 1;
        const int kc    = ci & 1;
        const int stage = ci & 1;
        const int pm0   = pmBase + tile*128;

        if (ci < NCHUNK-1) { CP_WAIT(1); } else { CP_WAIT(0); }
        __syncthreads();

        if (kc == 0) {
            #pragma unroll
            for (int s = 0; s < 2; ++s)
                #pragma unroll
                for (int mt = 0; mt < 4; ++mt)
                    #pragma unroll
                    for (int nt = 0; nt < 4; ++nt)
                        #pragma unroll
                        for (int j = 0; j < 4; ++j) acc[s][mt][nt][j] = 0.f;
        }

        const __nv_bfloat16* Ahi = (const __nv_bfloat16*)(dsm + MSA(stage, 0));
        const __nv_bfloat16* Alo = (const __nv_bfloat16*)(dsm + MSA(stage, 1));
        const __nv_bfloat16* Bhi0 = (const __nv_bfloat16*)(dsm + MSB(0,0));
        const __nv_bfloat16* Blo0 = (const __nv_bfloat16*)(dsm + MSB(0,1));
        const __nv_bfloat16* Bhi1 = (const __nv_bfloat16*)(dsm + MSB(1,0));
        const __nv_bfloat16* Blo1 = (const __nv_bfloat16*)(dsm + MSB(1,1));

        #pragma unroll
        for (int ks = 0; ks < 4; ++ks) {
            const int k0 = ks*16;
            const int kg = kc*64 + k0;
            uint32_t a[2][4][4];
            #pragma unroll
            for (int mt = 0; mt < 4; ++mt) {
                int r0 = warp_m*64 + mt*16 + g;
                const __nv_bfloat16* apH = Ahi + k0 + 2*t;
                const __nv_bfloat16* apL = Alo + k0 + 2*t;
                a[0][mt][0] = *(const uint32_t*)(apH + (size_t)r0*MASTR);
                a[0][mt][1] = *(const uint32_t*)(apH + (size_t)(r0+8)*MASTR);
                a[0][mt][2] = *(const uint32_t*)(apH + (size_t)r0*MASTR + 8);
                a[0][mt][3] = *(const uint32_t*)(apH + (size_t)(r0+8)*MASTR + 8);
                a[1][mt][0] = *(const uint32_t*)(apL + (size_t)r0*MASTR);
                a[1][mt][1] = *(const uint32_t*)(apL + (size_t)(r0+8)*MASTR);
                a[1][mt][2] = *(const uint32_t*)(apL + (size_t)r0*MASTR + 8);
                a[1][mt][3] = *(const uint32_t*)(apL + (size_t)(r0+8)*MASTR + 8);
            }
            #pragma unroll
            for (int s = 0; s < 2; ++s) {
                const __nv_bfloat16* BH = s ? Bhi1 : Bhi0;
                const __nv_bfloat16* BL = s ? Blo1 : Blo0;
                uint32_t bfr[2][4][2];
                #pragma unroll
                for (int nt = 0; nt < 4; ++nt) {
                    int n = warp_n*32 + nt*8 + g;
                    const __nv_bfloat16* bpH = BH + (size_t)n*MBSTR + kg + 2*t;
                    const __nv_bfloat16* bpL = BL + (size_t)n*MBSTR + kg + 2*t;
                    bfr[0][nt][0] = *(const uint32_t*)bpH;
                    bfr[0][nt][1] = *(const uint32_t*)(bpH + 8);
                    bfr[1][nt][0] = *(const uint32_t*)bpL;
                    bfr[1][nt][1] = *(const uint32_t*)(bpL + 8);
                }
                #pragma unroll
                for (int mt = 0; mt < 4; ++mt)
                    #pragma unroll
                    for (int nt = 0; nt < 4; ++nt) {
                        mma16816(acc[s][mt][nt], a[0][mt], bfr[0][nt][0], bfr[0][nt][1]);
                        mma16816(acc[s][mt][nt], a[1][mt], bfr[0][nt][0], bfr[0][nt][1]);
                        mma16816(acc[s][mt][nt], a[0][mt], bfr[1][nt][0], bfr[1][nt][1]);
                    }
            }
        }
        __syncthreads();

        if (ci + 2 < NCHUNK) {
            int nci = ci + 2;
            moe_loadA_chunk(smb, nci & 1, pmBase + (nci >> 1)*128, nci & 1, tid);
        }

        if (kc == 1) {
            #pragma unroll
            for (int mt = 0; mt < 4; ++mt) {
                int row = pm0 + warp_m*64 + mt*16 + g;
                #pragma unroll
                for (int nt = 0; nt < 4; ++nt) {
                    int col0 = warp_n*32 + nt*8 + 2*t;
                    float b00 = biasSm[col0],       b01 = biasSm[col0 + 1];
                    float b10 = biasSm[128 + col0], b11 = biasSm[128 + col0 + 1];
                    float o[4];
                    #pragma unroll
                    for (int j = 0; j < 4; ++j) {
                        float v0 = acc[0][mt][nt][j] + ((j & 1) ? b01 : b00);
                        float v1 = acc[1][mt][nt][j] + ((j & 1) ? b11 : b10);
                        o[j] = v0 + __logf(g0 + g1 * __expf(v1 - v0));
                    }
                    *(float2*)&out[(size_t)row*128 + col0]     = make_float2(o[0], o[1]);
                    *(float2*)&out[(size_t)(row+8)*128 + col0] = make_float2(o[2], o[3]);
                }
            }
        }
    }
}

// ---------------------------------------------------------------------------
// Launch
// ---------------------------------------------------------------------------
extern "C" void kernel_launch(void* const* d_in, const int* in_sizes, int n_in,
                              void* d_out, int out_size) {
    const float* x        = (const float*)d_in[0];
    const float* conv_w   = (const float*)d_in[1];
    const float* conv_b   = (const float*)d_in[2];
    const float* bn_gamma = (const float*)d_in[3];
    const float* bn_beta  = (const float*)d_in[4];
    const float* bn_mean  = (const float*)d_in[5];
    const float* bn_var   = (const float*)d_in[6];
    const float* fuse_w   = (const float*)d_in[7];
    const float* fuse_b   = (const float*)d_in[8];
    const float* w_gate   = (const float*)d_in[9];
    const float* expert_w = (const float*)d_in[10];
    const float* expert_b = (const float*)d_in[11];
    float* out = (float*)d_out;

    __nv_bfloat16 *xHi, *xLo, *aHi0, *aLo0, *aHi1, *aLo1;
    cudaGetSymbolAddress((void**)&xHi,  g_xHi);
    cudaGetSymbolAddress((void**)&xLo,  g_xLo);
    cudaGetSymbolAddress((void**)&aHi0, g_aHi0);
    cudaGetSymbolAddress((void**)&aLo0, g_aLo0);
    cudaGetSymbolAddress((void**)&aHi1, g_aHi1);
    cudaGetSymbolAddress((void**)&aLo1, g_aLo1);

    cudaFuncSetAttribute(conv_mma_kernel,
                         cudaFuncAttributeMaxDynamicSharedMemorySize, CV_SMEM);
    cudaFuncSetAttribute(conv_mma_small,
                         cudaFuncAttributeMaxDynamicSharedMemorySize, CS_SMEM);
    cudaFuncSetAttribute(conv_mma_fullk,
                         cudaFuncAttributeMaxDynamicSharedMemorySize, CF_SMEM);
    cudaFuncSetAttribute(moe_mma_kernel,
                         cudaFuncAttributeMaxDynamicSharedMemorySize, MOE_SMEM);

    prologue_split_kernel<<<(T1 + T2 + T3 + 255)/256, 256>>>(
        (const float4*)x, conv_w, expert_w);

    const __nv_bfloat16* iH = xHi;
    const __nv_bfloat16* iL = xLo;
    int Si = 32;
    for (int l = 0; l < N_CONV; ++l) {
        int So = Si >> 1;
        int M  = 96 * So * So;
        __nv_bfloat16* oH = (l & 1) ? aHi1 : aHi0;
        __nv_bfloat16* oL = (l & 1) ? aLo1 : aLo0;
        if (l == 0) {
            conv_mma_kernel<<<(M + 63)/64, 256, CV_SMEM>>>(iH, iL, oH, oL, Si, So, M, l,
                                                           conv_b   + l*128,
                                                           bn_gamma + l*128,
                                                           bn_beta  + l*128,
                                                           bn_mean  + l*128,
                                                           bn_var   + l*128);
        } else if (l <= 2) {
            conv_mma_small<<<(M + 15)/16, 256, CS_SMEM>>>(iH, iL, oH, oL, Si, So, M, l,
                                                          conv_b   + l*128,
                                                          bn_gamma + l*128,
                                                          bn_beta  + l*128,
                                                          bn_mean  + l*128,
                                                          bn_var   + l*128);
        } else {
            conv_mma_fullk<<<((M + 15)/16)*2, 256, CF_SMEM>>>(iH, iL, oH, oL, Si, So, M, l,
                                                              conv_b   + l*128,
                                                              bn_gamma + l*128,
                                                              bn_beta  + l*128,
                                                              bn_mean  + l*128,
                                                              bn_var   + l*128);
        }
        iH = oH; iL = oL;
        Si = So;
    }

    gates_kernel<<<1, 128>>>(aHi0, aLo0, fuse_w, fuse_b, w_gate);

    dim3 moeGrid(32, Bb);
    moe_mma_kernel<<<moeGrid, 256, MOE_SMEM>>>(expert_b, out);
}